// round 10
// baseline (speedup 1.0000x reference)
#include <cuda_runtime.h>
#include <cuda_fp16.h>
#include <math.h>
#include <stdint.h>

// Problem constants
#define L_SEQ   2048
#define DM      1024
#define DI      1024
#define DTR     64
#define DS      16
#define PROJ    (DTR + 2 * DI * DS)   // 32832
#define NPAD    32896                 // 257 * 128
#define KDIM    1024

// -------- scratch (static device globals; no allocation) --------
__device__ __half g_dbch[(size_t)L_SEQ * PROJ];     // B/C as fp16 (cols 0..63 unused)
__device__ float  g_dlr[(size_t)L_SEQ * DTR];       // exact fp32 delta_lr
__device__ float  g_delta[(size_t)L_SEQ * DI];
__device__ __half g_xf[(size_t)L_SEQ * DM];
__device__ __half g_wf[(size_t)NPAD * DM];
__device__ __half g_wof[(size_t)DM * DI];
__device__ __half g_yf[(size_t)L_SEQ * DI];

// ============================================================================
// helpers
// ============================================================================
__device__ __forceinline__ uint32_t smem_u32(const void* p) {
    uint32_t a;
    asm("{ .reg .u64 t; cvta.to.shared.u64 t, %1; cvt.u32.u64 %0, t; }" : "=r"(a) : "l"(p));
    return a;
}
__device__ __forceinline__ uint32_t swz128(uint32_t o) { return o ^ ((o >> 3) & 0x70); }

__device__ __forceinline__ void cp_async16(uint32_t dst, const void* src) {
    asm volatile("cp.async.cg.shared.global [%0], [%1], 16;" :: "r"(dst), "l"(src));
}
#define CP_COMMIT() asm volatile("cp.async.commit_group;" ::: "memory")
#define CP_WAIT(n)  asm volatile("cp.async.wait_group %0;" :: "n"(n) : "memory")

__device__ __forceinline__ void ldsm4(uint32_t* r, uint32_t addr) {
    asm volatile("ldmatrix.sync.aligned.m8n8.x4.shared.b16 {%0,%1,%2,%3}, [%4];"
        : "=r"(r[0]), "=r"(r[1]), "=r"(r[2]), "=r"(r[3]) : "r"(addr));
}
__device__ __forceinline__ void mma_f16(float* d, const uint32_t* a, const uint32_t* b) {
    asm volatile(
        "mma.sync.aligned.m16n8k16.row.col.f32.f16.f16.f32 "
        "{%0,%1,%2,%3}, {%4,%5,%6,%7}, {%8,%9}, {%0,%1,%2,%3};"
        : "+f"(d[0]), "+f"(d[1]), "+f"(d[2]), "+f"(d[3])
        : "r"(a[0]), "r"(a[1]), "r"(a[2]), "r"(a[3]), "r"(b[0]), "r"(b[1]));
}

// ============================================================================
// fp32 -> fp16 conversion (zero-pad beyond n_valid)
// ============================================================================
__global__ __launch_bounds__(256) void cvt16_kernel(
    const float* __restrict__ src, __half* __restrict__ dst,
    size_t n_valid, size_t n_total)
{
    size_t i = ((size_t)blockIdx.x * 256 + threadIdx.x) * 4;
    if (i >= n_total) return;
    float4 v = make_float4(0.f, 0.f, 0.f, 0.f);
    if (i < n_valid) v = *(const float4*)(src + i);
    *(__half2*)(dst + i)     = __floats2half2_rn(v.x, v.y);
    *(__half2*)(dst + i + 2) = __floats2half2_rn(v.z, v.w);
}

// ============================================================================
// FP16 GEMM: C[m,n] = A[m,:]·B[n,:]  (f32 accumulate)
// CTA 128x128, BK=64, 256 threads (8 warps 2x4, warp tile 64x32),
// 3-stage cp.async pipeline. Fragment loads software-pipelined:
// B double-buffered across ks, A double-buffered across mf, so LDSM
// issues overlap the HMMA stream instead of serializing with it.
// ============================================================================
#define F_ATILE  16384
#define F_STAGE  32768
#define F_NSTAGE 3
#define SMEM_F16_TOTAL (F_NSTAGE * F_STAGE)   // 96 KB
#define F_NKC    (KDIM / 64)        // 16

template<typename OT>
__global__ __launch_bounds__(256, 2) void gemm_f16(
    const __half* __restrict__ A, const __half* __restrict__ B,
    OT* __restrict__ C, int ldc, int nvalid)
{
    extern __shared__ char smem[];
    const uint32_t sbase = smem_u32(smem);
    const int tid = threadIdx.x;
    const int wid = tid >> 5, lane = tid & 31;
    const int wm = wid & 1, wn = wid >> 1;

    const int m0 = blockIdx.x * 128;
    const int n0 = blockIdx.y * 128;

    float acc[4][4][4];
    #pragma unroll
    for (int i = 0; i < 4; i++)
        #pragma unroll
        for (int j = 0; j < 4; j++)
            #pragma unroll
            for (int q = 0; q < 4; q++) acc[i][j][q] = 0.f;

    auto issue = [&](int kc) {
        if (kc < F_NKC) {
            const uint32_t soff = sbase + (kc % F_NSTAGE) * F_STAGE;
            #pragma unroll
            for (int j = 0; j < 4; j++) {
                const int q = tid * 4 + j;
                const int row = q >> 3, c = q & 7;
                const uint32_t so = swz128((uint32_t)(row * 128 + c * 16));
                const size_t ga = (size_t)(m0 + row) * KDIM + (size_t)kc * 64 + c * 8;
                const size_t gb = (size_t)(n0 + row) * KDIM + (size_t)kc * 64 + c * 8;
                cp_async16(soff + so, A + ga);
                cp_async16(soff + F_ATILE + so, B + gb);
            }
        }
        CP_COMMIT();
    };

    // precomputed fragment row/col components
    const int rb_base = wn * 32 + ((lane >> 4) << 3) + (lane & 7);
    const int cb_half = (lane >> 3) & 1;
    const int ra_base = wm * 64 + (lane & 15);
    const int ca_half = lane >> 4;

    issue(0);
    issue(1);

    #pragma unroll 1
    for (int kc = 0; kc < F_NKC; kc++) {
        if (kc + 1 < F_NKC) CP_WAIT(1); else CP_WAIT(0);
        __syncthreads();
        issue(kc + 2);

        const uint32_t sA = sbase + (kc % F_NSTAGE) * F_STAGE;

        uint32_t bcur[4][2], bnxt[4][2];
        uint32_t acur[4], anxt[4];

        // preload B(ks=0) and A(ks=0, mf=0)
        #pragma unroll
        for (int p = 0; p < 2; p++) {
            const int rowb = rb_base + p * 16;
            const int chb  = cb_half;
            ldsm4(&bcur[p * 2][0], sA + F_ATILE + swz128((uint32_t)(rowb * 128 + chb * 16)));
        }
        ldsm4(acur, sA + swz128((uint32_t)(ra_base * 128 + ca_half * 16)));

        #pragma unroll
        for (int ks = 0; ks < 4; ks++) {
            if (ks < 3) {
                #pragma unroll
                for (int p = 0; p < 2; p++) {
                    const int rowb = rb_base + p * 16;
                    const int chb  = (ks + 1) * 2 + cb_half;
                    ldsm4(&bnxt[p * 2][0],
                          sA + F_ATILE + swz128((uint32_t)(rowb * 128 + chb * 16)));
                }
            }
            #pragma unroll
            for (int mf = 0; mf < 4; mf++) {
                // prefetch the next A fragment (next mf, or mf=0 of next ks)
                const int nmf = (mf + 1) & 3;
                const int nks = (mf < 3) ? ks : ks + 1;
                if (nks < 4) {
                    const int rowa = ra_base + nmf * 16;
                    const int cha  = nks * 2 + ca_half;
                    ldsm4(anxt, sA + swz128((uint32_t)(rowa * 128 + cha * 16)));
                }
                #pragma unroll
                for (int nf = 0; nf < 4; nf++) mma_f16(acc[mf][nf], acur, bcur[nf]);
                #pragma unroll
                for (int q = 0; q < 4; q++) acur[q] = anxt[q];
            }
            if (ks < 3) {
                #pragma unroll
                for (int f = 0; f < 4; f++) {
                    bcur[f][0] = bnxt[f][0];
                    bcur[f][1] = bnxt[f][1];
                }
            }
        }
    }

    const int g = lane >> 2, t4 = lane & 3;
    #pragma unroll
    for (int mf = 0; mf < 4; mf++) {
        #pragma unroll
        for (int nf = 0; nf < 4; nf++) {
            const int m = m0 + wm * 64 + mf * 16 + g;
            const int n = n0 + wn * 32 + nf * 8 + t4 * 2;
            if (n < nvalid) {
                if constexpr (sizeof(OT) == 2) {
                    *(__half2*)((__half*)C + (size_t)m * ldc + n) =
                        __floats2half2_rn(acc[mf][nf][0], acc[mf][nf][1]);
                    *(__half2*)((__half*)C + (size_t)(m + 8) * ldc + n) =
                        __floats2half2_rn(acc[mf][nf][2], acc[mf][nf][3]);
                } else {
                    *(float2*)((float*)C + (size_t)m * ldc + n) =
                        make_float2(acc[mf][nf][0], acc[mf][nf][1]);
                    *(float2*)((float*)C + (size_t)(m + 8) * ldc + n) =
                        make_float2(acc[mf][nf][2], acc[mf][nf][3]);
                }
            }
        }
    }
}

// ============================================================================
// Exact fp32 delta_lr: dlr[t,k] = x[t,:]·W_in[k,:]
// ============================================================================
__global__ __launch_bounds__(256) void dlr_kernel(
    const float* __restrict__ x, const float* __restrict__ W_in)
{
    __shared__ float sx[64][36];
    __shared__ float sw[64][65];
    const int tid = threadIdx.x;
    const int k = tid & 63;
    const int tg = tid >> 6;
    const int t0 = blockIdx.x * 32;

    float acc[8];
    #pragma unroll
    for (int i = 0; i < 8; i++) acc[i] = 0.f;

    for (int kc = 0; kc < 16; kc++) {
        #pragma unroll
        for (int j = 0; j < 2; j++) {
            const int q = tid * 2 + j;
            const int t = q >> 4, c = q & 15;
            float4 v = *(const float4*)(x + (size_t)(t0 + t) * KDIM + kc * 64 + c * 4);
            sx[c * 4 + 0][t] = v.x; sx[c * 4 + 1][t] = v.y;
            sx[c * 4 + 2][t] = v.z; sx[c * 4 + 3][t] = v.w;
        }
        #pragma unroll
        for (int j = 0; j < 4; j++) {
            const int q = tid * 4 + j;
            const int k2 = q >> 4, c = q & 15;
            float4 v = *(const float4*)(W_in + (size_t)k2 * KDIM + kc * 64 + c * 4);
            sw[c * 4 + 0][k2] = v.x; sw[c * 4 + 1][k2] = v.y;
            sw[c * 4 + 2][k2] = v.z; sw[c * 4 + 3][k2] = v.w;
        }
        __syncthreads();
        #pragma unroll 16
        for (int kk = 0; kk < 64; kk++) {
            const float w = sw[kk][k];
            #pragma unroll
            for (int i = 0; i < 8; i++)
                acc[i] = fmaf(sx[kk][tg * 8 + i], w, acc[i]);
        }
        __syncthreads();
    }
    #pragma unroll
    for (int i = 0; i < 8; i++)
        g_dlr[(size_t)(t0 + tg * 8 + i) * DTR + k] = acc[i];
}

// ============================================================================
// delta[t,d] = softplus(g_dlr[t,:] · W_delta[d,:])
// ============================================================================
__global__ __launch_bounds__(128) void delta_kernel(const float* __restrict__ W_delta)
{
    __shared__ float s_dl[8][64];
    __shared__ float s_wT[64][129];
    const int tid = threadIdx.x;
    const int t0 = blockIdx.x * 8;
    const int d0 = blockIdx.y * 128;

    for (int i = tid; i < 8 * 64; i += 128) {
        int t = i >> 6, kk = i & 63;
        s_dl[t][kk] = g_dlr[(size_t)(t0 + t) * DTR + kk];
    }
    for (int i = tid; i < 128 * 64; i += 128) {
        int d = i >> 6, kk = i & 63;
        s_wT[kk][d] = W_delta[(size_t)(d0 + d) * DTR + kk];
    }
    __syncthreads();

    float accv[8];
    #pragma unroll
    for (int t = 0; t < 8; t++) accv[t] = 0.f;
    #pragma unroll 8
    for (int kk = 0; kk < 64; kk++) {
        float w = s_wT[kk][tid];
        #pragma unroll
        for (int t = 0; t < 8; t++) accv[t] = fmaf(s_dl[t][kk], w, accv[t]);
    }
    #pragma unroll
    for (int t = 0; t < 8; t++) {
        float z = accv[t];
        float sp = fmaxf(z, 0.f) + log1pf(__expf(-fabsf(z)));
        g_delta[(size_t)(t0 + t) * DI + d0 + tid] = sp;
    }
}

// ============================================================================
// Selective scan v2: cp.async smem-staged, 32-step chunks, 4-stage ring.
// ============================================================================
#define SC_T      32
#define SC_NCH    (L_SEQ / SC_T)
#define SC_BBYTES (SC_T * 256)
#define SC_DBYTES (SC_T * 32)
#define SC_B_OFF  0
#define SC_C_OFF  SC_BBYTES
#define SC_D_OFF  (2 * SC_BBYTES)
#define SC_X_OFF  (2 * SC_BBYTES + SC_DBYTES)
#define SC_STAGE  (2 * SC_BBYTES + 2 * SC_DBYTES)
#define SC_NSTAGE 4
#define SMEM_SCAN_TOTAL (SC_NSTAGE * SC_STAGE)

__global__ __launch_bounds__(128) void scan_kernel(
    const float* __restrict__ x, const float* __restrict__ A_log,
    const float* __restrict__ Dv)
{
    extern __shared__ char smem[];
    const uint32_t sbase = smem_u32(smem);
    const int tid = threadIdx.x;
    const int blk = blockIdx.x;
    const int lc = tid >> 4, s = tid & 15;
    const int d = blk * 8 + lc;

    const float a = -expf(A_log[d * DS + s]);
    const float Dd = Dv[d];

    const char* gB = (const char*)(g_dbch + DTR + (size_t)blk * 128);
    const char* gC = (const char*)(g_dbch + DTR + DI * DS + (size_t)blk * 128);
    const char* gD = (const char*)(g_delta + (size_t)blk * 8);
    const char* gX = (const char*)(x + (size_t)blk * 8);

    auto issue = [&](int ch) {
        if (ch < SC_NCH) {
            const uint32_t soff = sbase + (ch & 3) * SC_STAGE;
            const size_t t0 = (size_t)ch * SC_T;
            #pragma unroll
            for (int j = 0; j < 4; j++) {
                const int q = tid * 4 + j;
                const int st = q >> 4, off = (q & 15) * 16;
                cp_async16(soff + SC_B_OFF + st * 256 + off,
                           gB + (t0 + st) * (PROJ * 2) + off);
                cp_async16(soff + SC_C_OFF + st * 256 + off,
                           gC + (t0 + st) * (PROJ * 2) + off);
            }
            {
                const int q = tid & 63;
                const int st = q >> 1, off = (q & 1) * 16;
                if (tid < 64)
                    cp_async16(soff + SC_D_OFF + st * 32 + off,
                               gD + (t0 + st) * (DI * 4) + off);
                else
                    cp_async16(soff + SC_X_OFF + st * 32 + off,
                               gX + (t0 + st) * (DI * 4) + off);
            }
        }
        CP_COMMIT();
    };

    issue(0); issue(1); issue(2);

    float h = 0.f;
    #pragma unroll 1
    for (int ch = 0; ch < SC_NCH; ch++) {
        CP_WAIT(2);
        __syncthreads();
        issue(ch + 3);

        const uint32_t so = (ch & 3) * SC_STAGE;
        const __half* sB = (const __half*)(smem + so + SC_B_OFF);
        const __half* sC = (const __half*)(smem + so + SC_C_OFF);
        const float* sD  = (const float*)(smem + so + SC_D_OFF);
        const float* sX  = (const float*)(smem + so + SC_X_OFF);
        const int tbase = ch * SC_T;

        #pragma unroll 8
        for (int st = 0; st < SC_T; st++) {
            const float Bv = __half2float(sB[st * 128 + tid]);
            const float Cv = __half2float(sC[st * 128 + tid]);
            const float dt = sD[st * 8 + lc];
            const float xt = sX[st * 8 + lc];
            h = fmaf(__expf(dt * a), h, dt * xt * Bv);
            float yv = h * Cv;
            yv += __shfl_xor_sync(0xffffffffu, yv, 1);
            yv += __shfl_xor_sync(0xffffffffu, yv, 2);
            yv += __shfl_xor_sync(0xffffffffu, yv, 4);
            yv += __shfl_xor_sync(0xffffffffu, yv, 8);
            if (s == 0)
                g_yf[(size_t)(tbase + st) * DI + d] =
                    __float2half_rn(fmaf(xt, Dd, yv));
        }
    }
}

// ============================================================================
// Launch
// ============================================================================
extern "C" void kernel_launch(void* const* d_in, const int* in_sizes, int n_in,
                              void* d_out, int out_size)
{
    const float* x       = (const float*)d_in[0];
    const float* W_in    = (const float*)d_in[1];
    const float* W_delta = (const float*)d_in[2];
    const float* A_log   = (const float*)d_in[3];
    const float* Dv      = (const float*)d_in[4];
    const float* W_out   = (const float*)d_in[5];
    float* out = (float*)d_out;

    __half *dbch, *xf, *wf, *wof, *yf;
    cudaGetSymbolAddress((void**)&dbch, g_dbch);
    cudaGetSymbolAddress((void**)&xf, g_xf);
    cudaGetSymbolAddress((void**)&wf, g_wf);
    cudaGetSymbolAddress((void**)&wof, g_wof);
    cudaGetSymbolAddress((void**)&yf, g_yf);

    cudaFuncSetAttribute(gemm_f16<__half>, cudaFuncAttributeMaxDynamicSharedMemorySize,
                         SMEM_F16_TOTAL);
    cudaFuncSetAttribute(gemm_f16<float>, cudaFuncAttributeMaxDynamicSharedMemorySize,
                         SMEM_F16_TOTAL);
    cudaFuncSetAttribute(scan_kernel, cudaFuncAttributeMaxDynamicSharedMemorySize,
                         SMEM_SCAN_TOTAL);

    // 1) conversions
    {
        size_t nx = (size_t)L_SEQ * DM;
        cvt16_kernel<<<(unsigned)((nx / 4 + 255) / 256), 256>>>(x, xf, nx, nx);
        size_t nwv = (size_t)PROJ * DM, nwt = (size_t)NPAD * DM;
        cvt16_kernel<<<(unsigned)((nwt / 4 + 255) / 256), 256>>>(W_in, wf, nwv, nwt);
        size_t nwo = (size_t)DM * DI;
        cvt16_kernel<<<(unsigned)((nwo / 4 + 255) / 256), 256>>>(W_out, wof, nwo, nwo);
    }
    // 2) dbc (B/C) = x @ W_in^T  -> fp16 output
    {
        dim3 grid(L_SEQ / 128, NPAD / 128);
        gemm_f16<__half><<<grid, 256, SMEM_F16_TOTAL>>>(xf, wf, dbch, PROJ, PROJ);
    }
    // 3) exact fp32 delta_lr
    dlr_kernel<<<L_SEQ / 32, 256>>>(x, W_in);
    // 4) delta
    {
        dim3 grid(L_SEQ / 8, DI / 128);
        delta_kernel<<<grid, 128>>>(W_delta);
    }
    // 5) scan v2 (smem-staged)
    scan_kernel<<<128, 128, SMEM_SCAN_TOTAL>>>(x, A_log, Dv);
    // 6) out = y @ W_out^T  -> f32 output
    {
        dim3 grid(L_SEQ / 128, DM / 128);
        gemm_f16<float><<<grid, 256, SMEM_F16_TOTAL>>>(yf, wof, out, DM, DM);
    }
}

// round 11
// speedup vs baseline: 1.0524x; 1.0524x over previous
#include <cuda_runtime.h>
#include <cuda_fp16.h>
#include <math.h>
#include <stdint.h>

// Problem constants
#define L_SEQ   2048
#define DM      1024
#define DI      1024
#define DTR     64
#define DS      16
#define PROJ    (DTR + 2 * DI * DS)   // 32832
#define NPAD    32896                 // 257 * 128
#define KDIM    1024

// -------- scratch (static device globals; no allocation) --------
__device__ __half g_dbch[(size_t)L_SEQ * PROJ];     // B/C as fp16 (cols 0..63 unused)
__device__ float  g_dlr[(size_t)L_SEQ * DTR];       // exact fp32 delta_lr
__device__ float  g_delta[(size_t)L_SEQ * DI];
__device__ __half g_xf[(size_t)L_SEQ * DM];
__device__ __half g_wf[(size_t)NPAD * DM];
__device__ __half g_wof[(size_t)DM * DI];
__device__ __half g_yf[(size_t)L_SEQ * DI];

// ============================================================================
// helpers
// ============================================================================
__device__ __forceinline__ uint32_t smem_u32(const void* p) {
    uint32_t a;
    asm("{ .reg .u64 t; cvta.to.shared.u64 t, %1; cvt.u32.u64 %0, t; }" : "=r"(a) : "l"(p));
    return a;
}
__device__ __forceinline__ uint32_t swz128(uint32_t o) { return o ^ ((o >> 3) & 0x70); }

__device__ __forceinline__ void cp_async16(uint32_t dst, const void* src) {
    asm volatile("cp.async.cg.shared.global [%0], [%1], 16;" :: "r"(dst), "l"(src));
}
#define CP_COMMIT() asm volatile("cp.async.commit_group;" ::: "memory")
#define CP_WAIT(n)  asm volatile("cp.async.wait_group %0;" :: "n"(n) : "memory")

__device__ __forceinline__ void ldsm4(uint32_t* r, uint32_t addr) {
    asm volatile("ldmatrix.sync.aligned.m8n8.x4.shared.b16 {%0,%1,%2,%3}, [%4];"
        : "=r"(r[0]), "=r"(r[1]), "=r"(r[2]), "=r"(r[3]) : "r"(addr));
}
__device__ __forceinline__ void mma_f16(float* d, const uint32_t* a, const uint32_t* b) {
    asm volatile(
        "mma.sync.aligned.m16n8k16.row.col.f32.f16.f16.f32 "
        "{%0,%1,%2,%3}, {%4,%5,%6,%7}, {%8,%9}, {%0,%1,%2,%3};"
        : "+f"(d[0]), "+f"(d[1]), "+f"(d[2]), "+f"(d[3])
        : "r"(a[0]), "r"(a[1]), "r"(a[2]), "r"(a[3]), "r"(b[0]), "r"(b[1]));
}

// ============================================================================
// fp32 -> fp16 conversion (zero-pad beyond n_valid)
// ============================================================================
__global__ __launch_bounds__(256) void cvt16_kernel(
    const float* __restrict__ src, __half* __restrict__ dst,
    size_t n_valid, size_t n_total)
{
    size_t i = ((size_t)blockIdx.x * 256 + threadIdx.x) * 4;
    if (i >= n_total) return;
    float4 v = make_float4(0.f, 0.f, 0.f, 0.f);
    if (i < n_valid) v = *(const float4*)(src + i);
    *(__half2*)(dst + i)     = __floats2half2_rn(v.x, v.y);
    *(__half2*)(dst + i + 2) = __floats2half2_rn(v.z, v.w);
}

// ============================================================================
// FP16 GEMM v3: C[m,n] = A[m,:]·B[n,:]  (f32 accumulate)
// CTA 128x128, BK=64, 512 threads (16 warps, grid 4x4, warp tile 32x32),
// 3-stage cp.async pipeline. 64 regs/thread -> 2 CTAs/SM = 32 warps/SM.
// ============================================================================
#define F_ATILE  16384
#define F_STAGE  32768
#define F_NSTAGE 3
#define SMEM_F16_TOTAL (F_NSTAGE * F_STAGE)   // 96 KB
#define F_NKC    (KDIM / 64)        // 16

template<typename OT>
__global__ __launch_bounds__(512, 2) void gemm_f16(
    const __half* __restrict__ A, const __half* __restrict__ B,
    OT* __restrict__ C, int ldc, int nvalid)
{
    extern __shared__ char smem[];
    const uint32_t sbase = smem_u32(smem);
    const int tid = threadIdx.x;
    const int wid = tid >> 5, lane = tid & 31;
    const int wm = wid & 3, wn = wid >> 2;       // warp grid 4 (m) x 4 (n)

    const int m0 = blockIdx.x * 128;
    const int n0 = blockIdx.y * 128;

    float acc[2][4][4];
    #pragma unroll
    for (int i = 0; i < 2; i++)
        #pragma unroll
        for (int j = 0; j < 4; j++)
            #pragma unroll
            for (int q = 0; q < 4; q++) acc[i][j][q] = 0.f;

    auto issue = [&](int kc) {
        if (kc < F_NKC) {
            const uint32_t soff = sbase + (kc % F_NSTAGE) * F_STAGE;
            #pragma unroll
            for (int j = 0; j < 2; j++) {
                const int q = tid * 2 + j;          // 0..1023
                const int row = q >> 3, c = q & 7;
                const uint32_t so = swz128((uint32_t)(row * 128 + c * 16));
                const size_t ga = (size_t)(m0 + row) * KDIM + (size_t)kc * 64 + c * 8;
                const size_t gb = (size_t)(n0 + row) * KDIM + (size_t)kc * 64 + c * 8;
                cp_async16(soff + so, A + ga);
                cp_async16(soff + F_ATILE + so, B + gb);
            }
        }
        CP_COMMIT();
    };

    const int rb_base = wn * 32 + ((lane >> 4) << 3) + (lane & 7);
    const int cb_half = (lane >> 3) & 1;
    const int ra_base = wm * 32 + (lane & 15);
    const int ca_half = lane >> 4;

    issue(0);
    issue(1);

    #pragma unroll 1
    for (int kc = 0; kc < F_NKC; kc++) {
        if (kc + 1 < F_NKC) CP_WAIT(1); else CP_WAIT(0);
        __syncthreads();
        issue(kc + 2);

        const uint32_t sA = sbase + (kc % F_NSTAGE) * F_STAGE;

        #pragma unroll
        for (int ks = 0; ks < 4; ks++) {
            uint32_t bf[4][2];
            #pragma unroll
            for (int p = 0; p < 2; p++) {
                const int rowb = rb_base + p * 16;
                const int chb  = ks * 2 + cb_half;
                ldsm4(&bf[p * 2][0],
                      sA + F_ATILE + swz128((uint32_t)(rowb * 128 + chb * 16)));
            }
            #pragma unroll
            for (int mf = 0; mf < 2; mf++) {
                const int rowa = ra_base + mf * 16;
                const int cha  = ks * 2 + ca_half;
                uint32_t af[4];
                ldsm4(af, sA + swz128((uint32_t)(rowa * 128 + cha * 16)));
                #pragma unroll
                for (int nf = 0; nf < 4; nf++) mma_f16(acc[mf][nf], af, bf[nf]);
            }
        }
    }

    const int g = lane >> 2, t4 = lane & 3;
    #pragma unroll
    for (int mf = 0; mf < 2; mf++) {
        #pragma unroll
        for (int nf = 0; nf < 4; nf++) {
            const int m = m0 + wm * 32 + mf * 16 + g;
            const int n = n0 + wn * 32 + nf * 8 + t4 * 2;
            if (n < nvalid) {
                if constexpr (sizeof(OT) == 2) {
                    *(__half2*)((__half*)C + (size_t)m * ldc + n) =
                        __floats2half2_rn(acc[mf][nf][0], acc[mf][nf][1]);
                    *(__half2*)((__half*)C + (size_t)(m + 8) * ldc + n) =
                        __floats2half2_rn(acc[mf][nf][2], acc[mf][nf][3]);
                } else {
                    *(float2*)((float*)C + (size_t)m * ldc + n) =
                        make_float2(acc[mf][nf][0], acc[mf][nf][1]);
                    *(float2*)((float*)C + (size_t)(m + 8) * ldc + n) =
                        make_float2(acc[mf][nf][2], acc[mf][nf][3]);
                }
            }
        }
    }
}

// ============================================================================
// Exact fp32 delta_lr: dlr[t,k] = x[t,:]·W_in[k,:]
// ============================================================================
__global__ __launch_bounds__(256) void dlr_kernel(
    const float* __restrict__ x, const float* __restrict__ W_in)
{
    __shared__ float sx[64][36];
    __shared__ float sw[64][65];
    const int tid = threadIdx.x;
    const int k = tid & 63;
    const int tg = tid >> 6;
    const int t0 = blockIdx.x * 32;

    float acc[8];
    #pragma unroll
    for (int i = 0; i < 8; i++) acc[i] = 0.f;

    for (int kc = 0; kc < 16; kc++) {
        #pragma unroll
        for (int j = 0; j < 2; j++) {
            const int q = tid * 2 + j;
            const int t = q >> 4, c = q & 15;
            float4 v = *(const float4*)(x + (size_t)(t0 + t) * KDIM + kc * 64 + c * 4);
            sx[c * 4 + 0][t] = v.x; sx[c * 4 + 1][t] = v.y;
            sx[c * 4 + 2][t] = v.z; sx[c * 4 + 3][t] = v.w;
        }
        #pragma unroll
        for (int j = 0; j < 4; j++) {
            const int q = tid * 4 + j;
            const int k2 = q >> 4, c = q & 15;
            float4 v = *(const float4*)(W_in + (size_t)k2 * KDIM + kc * 64 + c * 4);
            sw[c * 4 + 0][k2] = v.x; sw[c * 4 + 1][k2] = v.y;
            sw[c * 4 + 2][k2] = v.z; sw[c * 4 + 3][k2] = v.w;
        }
        __syncthreads();
        #pragma unroll 16
        for (int kk = 0; kk < 64; kk++) {
            const float w = sw[kk][k];
            #pragma unroll
            for (int i = 0; i < 8; i++)
                acc[i] = fmaf(sx[kk][tg * 8 + i], w, acc[i]);
        }
        __syncthreads();
    }
    #pragma unroll
    for (int i = 0; i < 8; i++)
        g_dlr[(size_t)(t0 + tg * 8 + i) * DTR + k] = acc[i];
}

// ============================================================================
// delta[t,d] = softplus(g_dlr[t,:] · W_delta[d,:])
// ============================================================================
__global__ __launch_bounds__(128) void delta_kernel(const float* __restrict__ W_delta)
{
    __shared__ float s_dl[8][64];
    __shared__ float s_wT[64][129];
    const int tid = threadIdx.x;
    const int t0 = blockIdx.x * 8;
    const int d0 = blockIdx.y * 128;

    for (int i = tid; i < 8 * 64; i += 128) {
        int t = i >> 6, kk = i & 63;
        s_dl[t][kk] = g_dlr[(size_t)(t0 + t) * DTR + kk];
    }
    for (int i = tid; i < 128 * 64; i += 128) {
        int d = i >> 6, kk = i & 63;
        s_wT[kk][d] = W_delta[(size_t)(d0 + d) * DTR + kk];
    }
    __syncthreads();

    float accv[8];
    #pragma unroll
    for (int t = 0; t < 8; t++) accv[t] = 0.f;
    #pragma unroll 8
    for (int kk = 0; kk < 64; kk++) {
        float w = s_wT[kk][tid];
        #pragma unroll
        for (int t = 0; t < 8; t++) accv[t] = fmaf(s_dl[t][kk], w, accv[t]);
    }
    #pragma unroll
    for (int t = 0; t < 8; t++) {
        float z = accv[t];
        float sp = fmaxf(z, 0.f) + log1pf(__expf(-fabsf(z)));
        g_delta[(size_t)(t0 + t) * DI + d0 + tid] = sp;
    }
}

// ============================================================================
// Selective scan v2: cp.async smem-staged, 32-step chunks, 4-stage ring.
// ============================================================================
#define SC_T      32
#define SC_NCH    (L_SEQ / SC_T)
#define SC_BBYTES (SC_T * 256)
#define SC_DBYTES (SC_T * 32)
#define SC_B_OFF  0
#define SC_C_OFF  SC_BBYTES
#define SC_D_OFF  (2 * SC_BBYTES)
#define SC_X_OFF  (2 * SC_BBYTES + SC_DBYTES)
#define SC_STAGE  (2 * SC_BBYTES + 2 * SC_DBYTES)
#define SC_NSTAGE 4
#define SMEM_SCAN_TOTAL (SC_NSTAGE * SC_STAGE)

__global__ __launch_bounds__(128) void scan_kernel(
    const float* __restrict__ x, const float* __restrict__ A_log,
    const float* __restrict__ Dv)
{
    extern __shared__ char smem[];
    const uint32_t sbase = smem_u32(smem);
    const int tid = threadIdx.x;
    const int blk = blockIdx.x;
    const int lc = tid >> 4, s = tid & 15;
    const int d = blk * 8 + lc;

    const float a = -expf(A_log[d * DS + s]);
    const float Dd = Dv[d];

    const char* gB = (const char*)(g_dbch + DTR + (size_t)blk * 128);
    const char* gC = (const char*)(g_dbch + DTR + DI * DS + (size_t)blk * 128);
    const char* gD = (const char*)(g_delta + (size_t)blk * 8);
    const char* gX = (const char*)(x + (size_t)blk * 8);

    auto issue = [&](int ch) {
        if (ch < SC_NCH) {
            const uint32_t soff = sbase + (ch & 3) * SC_STAGE;
            const size_t t0 = (size_t)ch * SC_T;
            #pragma unroll
            for (int j = 0; j < 4; j++) {
                const int q = tid * 4 + j;
                const int st = q >> 4, off = (q & 15) * 16;
                cp_async16(soff + SC_B_OFF + st * 256 + off,
                           gB + (t0 + st) * (PROJ * 2) + off);
                cp_async16(soff + SC_C_OFF + st * 256 + off,
                           gC + (t0 + st) * (PROJ * 2) + off);
            }
            {
                const int q = tid & 63;
                const int st = q >> 1, off = (q & 1) * 16;
                if (tid < 64)
                    cp_async16(soff + SC_D_OFF + st * 32 + off,
                               gD + (t0 + st) * (DI * 4) + off);
                else
                    cp_async16(soff + SC_X_OFF + st * 32 + off,
                               gX + (t0 + st) * (DI * 4) + off);
            }
        }
        CP_COMMIT();
    };

    issue(0); issue(1); issue(2);

    float h = 0.f;
    #pragma unroll 1
    for (int ch = 0; ch < SC_NCH; ch++) {
        CP_WAIT(2);
        __syncthreads();
        issue(ch + 3);

        const uint32_t so = (ch & 3) * SC_STAGE;
        const __half* sB = (const __half*)(smem + so + SC_B_OFF);
        const __half* sC = (const __half*)(smem + so + SC_C_OFF);
        const float* sD  = (const float*)(smem + so + SC_D_OFF);
        const float* sX  = (const float*)(smem + so + SC_X_OFF);
        const int tbase = ch * SC_T;

        #pragma unroll 8
        for (int st = 0; st < SC_T; st++) {
            const float Bv = __half2float(sB[st * 128 + tid]);
            const float Cv = __half2float(sC[st * 128 + tid]);
            const float dt = sD[st * 8 + lc];
            const float xt = sX[st * 8 + lc];
            h = fmaf(__expf(dt * a), h, dt * xt * Bv);
            float yv = h * Cv;
            yv += __shfl_xor_sync(0xffffffffu, yv, 1);
            yv += __shfl_xor_sync(0xffffffffu, yv, 2);
            yv += __shfl_xor_sync(0xffffffffu, yv, 4);
            yv += __shfl_xor_sync(0xffffffffu, yv, 8);
            if (s == 0)
                g_yf[(size_t)(tbase + st) * DI + d] =
                    __float2half_rn(fmaf(xt, Dd, yv));
        }
    }
}

// ============================================================================
// Launch
// ============================================================================
extern "C" void kernel_launch(void* const* d_in, const int* in_sizes, int n_in,
                              void* d_out, int out_size)
{
    const float* x       = (const float*)d_in[0];
    const float* W_in    = (const float*)d_in[1];
    const float* W_delta = (const float*)d_in[2];
    const float* A_log   = (const float*)d_in[3];
    const float* Dv      = (const float*)d_in[4];
    const float* W_out   = (const float*)d_in[5];
    float* out = (float*)d_out;

    __half *dbch, *xf, *wf, *wof, *yf;
    cudaGetSymbolAddress((void**)&dbch, g_dbch);
    cudaGetSymbolAddress((void**)&xf, g_xf);
    cudaGetSymbolAddress((void**)&wf, g_wf);
    cudaGetSymbolAddress((void**)&wof, g_wof);
    cudaGetSymbolAddress((void**)&yf, g_yf);

    cudaFuncSetAttribute(gemm_f16<__half>, cudaFuncAttributeMaxDynamicSharedMemorySize,
                         SMEM_F16_TOTAL);
    cudaFuncSetAttribute(gemm_f16<float>, cudaFuncAttributeMaxDynamicSharedMemorySize,
                         SMEM_F16_TOTAL);
    cudaFuncSetAttribute(scan_kernel, cudaFuncAttributeMaxDynamicSharedMemorySize,
                         SMEM_SCAN_TOTAL);

    // 1) conversions
    {
        size_t nx = (size_t)L_SEQ * DM;
        cvt16_kernel<<<(unsigned)((nx / 4 + 255) / 256), 256>>>(x, xf, nx, nx);
        size_t nwv = (size_t)PROJ * DM, nwt = (size_t)NPAD * DM;
        cvt16_kernel<<<(unsigned)((nwt / 4 + 255) / 256), 256>>>(W_in, wf, nwv, nwt);
        size_t nwo = (size_t)DM * DI;
        cvt16_kernel<<<(unsigned)((nwo / 4 + 255) / 256), 256>>>(W_out, wof, nwo, nwo);
    }
    // 2) dbc (B/C) = x @ W_in^T  -> fp16 output
    {
        dim3 grid(L_SEQ / 128, NPAD / 128);
        gemm_f16<__half><<<grid, 512, SMEM_F16_TOTAL>>>(xf, wf, dbch, PROJ, PROJ);
    }
    // 3) exact fp32 delta_lr
    dlr_kernel<<<L_SEQ / 32, 256>>>(x, W_in);
    // 4) delta
    {
        dim3 grid(L_SEQ / 8, DI / 128);
        delta_kernel<<<grid, 128>>>(W_delta);
    }
    // 5) scan v2 (smem-staged)
    scan_kernel<<<128, 128, SMEM_SCAN_TOTAL>>>(x, A_log, Dv);
    // 6) out = y @ W_out^T  -> f32 output
    {
        dim3 grid(L_SEQ / 128, DM / 128);
        gemm_f16<float><<<grid, 512, SMEM_F16_TOTAL>>>(yf, wof, out, DM, DM);
    }
}

// round 13
// speedup vs baseline: 1.0831x; 1.0292x over previous
#include <cuda_runtime.h>
#include <cuda_fp16.h>
#include <math.h>
#include <stdint.h>

// Problem constants
#define L_SEQ   2048
#define DM      1024
#define DI      1024
#define DTR     64
#define DS      16
#define PROJ    (DTR + 2 * DI * DS)   // 32832
#define BCW     32768                 // compact B/C width = 256 * 128
#define KDIM    1024

// -------- scratch (static device globals; no allocation) --------
__device__ __half g_bch[(size_t)L_SEQ * BCW];       // [B | C] per row, fp16
__device__ float  g_dlr[(size_t)L_SEQ * DTR];       // exact fp32 delta_lr
__device__ float  g_delta[(size_t)L_SEQ * DI];
__device__ __half g_xf[(size_t)L_SEQ * DM];
__device__ __half g_wf[(size_t)BCW * DM];           // W_in rows 64..32831
__device__ __half g_wof[(size_t)DM * DI];
__device__ __half g_yf[(size_t)L_SEQ * DI];

// ============================================================================
// helpers
// ============================================================================
__device__ __forceinline__ uint32_t smem_u32(const void* p) {
    uint32_t a;
    asm("{ .reg .u64 t; cvta.to.shared.u64 t, %1; cvt.u32.u64 %0, t; }" : "=r"(a) : "l"(p));
    return a;
}
__device__ __forceinline__ uint32_t swz128(uint32_t o) { return o ^ ((o >> 3) & 0x70); }

__device__ __forceinline__ void cp_async16(uint32_t dst, const void* src) {
    asm volatile("cp.async.cg.shared.global [%0], [%1], 16;" :: "r"(dst), "l"(src));
}
#define CP_COMMIT() asm volatile("cp.async.commit_group;" ::: "memory")
#define CP_WAIT(n)  asm volatile("cp.async.wait_group %0;" :: "n"(n) : "memory")

__device__ __forceinline__ void ldsm4(uint32_t* r, uint32_t addr) {
    asm volatile("ldmatrix.sync.aligned.m8n8.x4.shared.b16 {%0,%1,%2,%3}, [%4];"
        : "=r"(r[0]), "=r"(r[1]), "=r"(r[2]), "=r"(r[3]) : "r"(addr));
}
__device__ __forceinline__ void mma_f16(float* d, const uint32_t* a, const uint32_t* b) {
    asm volatile(
        "mma.sync.aligned.m16n8k16.row.col.f32.f16.f16.f32 "
        "{%0,%1,%2,%3}, {%4,%5,%6,%7}, {%8,%9}, {%0,%1,%2,%3};"
        : "+f"(d[0]), "+f"(d[1]), "+f"(d[2]), "+f"(d[3])
        : "r"(a[0]), "r"(a[1]), "r"(a[2]), "r"(a[3]), "r"(b[0]), "r"(b[1]));
}

// ============================================================================
// fp32 -> fp16 conversion
// ============================================================================
__global__ __launch_bounds__(256) void cvt16_kernel(
    const float* __restrict__ src, __half* __restrict__ dst, size_t n)
{
    size_t i = ((size_t)blockIdx.x * 256 + threadIdx.x) * 4;
    if (i >= n) return;
    float4 v = *(const float4*)(src + i);
    *(__half2*)(dst + i)     = __floats2half2_rn(v.x, v.y);
    *(__half2*)(dst + i + 2) = __floats2half2_rn(v.z, v.w);
}

// ============================================================================
// FP16 GEMM v4: C[m,n] = A[m,:]·B[n,:]  (f32 accumulate)
// CTA 128x128, BK=64, 512 threads (16 warps, grid 4x4, warp tile 32x32),
// 3-stage cp.async pipeline, 2 CTAs/SM (64 regs). Per-warp ks rotation
// (by wn) de-phases LDSM bursts within each SMSP so the shared crossbar
// and tensor pipe run concurrently instead of convoying.
// All tile edges exact: no epilogue guards.
// ============================================================================
#define F_ATILE  16384
#define F_STAGE  32768
#define F_NSTAGE 3
#define SMEM_F16_TOTAL (F_NSTAGE * F_STAGE)   // 96 KB
#define F_NKC    (KDIM / 64)        // 16

template<typename OT>
__global__ __launch_bounds__(512, 2) void gemm_f16(
    const __half* __restrict__ A, const __half* __restrict__ B,
    OT* __restrict__ C, int ldc)
{
    extern __shared__ char smem[];
    const uint32_t sbase = smem_u32(smem);
    const int tid = threadIdx.x;
    const int wid = tid >> 5, lane = tid & 31;
    const int wm = wid & 3, wn = wid >> 2;       // warp grid 4 (m) x 4 (n)

    const int m0 = blockIdx.x * 128;
    const int n0 = blockIdx.y * 128;

    float acc[2][4][4];
    #pragma unroll
    for (int i = 0; i < 2; i++)
        #pragma unroll
        for (int j = 0; j < 4; j++)
            #pragma unroll
            for (int q = 0; q < 4; q++) acc[i][j][q] = 0.f;

    auto issue = [&](int kc) {
        if (kc < F_NKC) {
            const uint32_t soff = sbase + (kc % F_NSTAGE) * F_STAGE;
            #pragma unroll
            for (int j = 0; j < 2; j++) {
                const int q = tid * 2 + j;          // 0..1023
                const int row = q >> 3, c = q & 7;
                const uint32_t so = swz128((uint32_t)(row * 128 + c * 16));
                const size_t ga = (size_t)(m0 + row) * KDIM + (size_t)kc * 64 + c * 8;
                const size_t gb = (size_t)(n0 + row) * KDIM + (size_t)kc * 64 + c * 8;
                cp_async16(soff + so, A + ga);
                cp_async16(soff + F_ATILE + so, B + gb);
            }
        }
        CP_COMMIT();
    };

    const int rb_base = wn * 32 + ((lane >> 4) << 3) + (lane & 7);
    const int cb_half = (lane >> 3) & 1;
    const int ra_base = wm * 32 + (lane & 15);
    const int ca_half = lane >> 4;
    const int ksr = wn;                          // per-SMSP phase stagger

    issue(0);
    issue(1);

    #pragma unroll 1
    for (int kc = 0; kc < F_NKC; kc++) {
        if (kc + 1 < F_NKC) CP_WAIT(1); else CP_WAIT(0);
        __syncthreads();
        issue(kc + 2);

        const uint32_t sA = sbase + (kc % F_NSTAGE) * F_STAGE;

        #pragma unroll
        for (int kss = 0; kss < 4; kss++) {
            const int ks = (kss + ksr) & 3;      // rotated k-substep
            uint32_t bf[4][2];
            #pragma unroll
            for (int p = 0; p < 2; p++) {
                const int rowb = rb_base + p * 16;
                const int chb  = ks * 2 + cb_half;
                ldsm4(&bf[p * 2][0],
                      sA + F_ATILE + swz128((uint32_t)(rowb * 128 + chb * 16)));
            }
            #pragma unroll
            for (int mf = 0; mf < 2; mf++) {
                const int rowa = ra_base + mf * 16;
                const int cha  = ks * 2 + ca_half;
                uint32_t af[4];
                ldsm4(af, sA + swz128((uint32_t)(rowa * 128 + cha * 16)));
                #pragma unroll
                for (int nf = 0; nf < 4; nf++) mma_f16(acc[mf][nf], af, bf[nf]);
            }
        }
    }

    const int g = lane >> 2, t4 = lane & 3;
    #pragma unroll
    for (int mf = 0; mf < 2; mf++) {
        #pragma unroll
        for (int nf = 0; nf < 4; nf++) {
            const int m = m0 + wm * 32 + mf * 16 + g;
            const int n = n0 + wn * 32 + nf * 8 + t4 * 2;
            if constexpr (sizeof(OT) == 2) {
                *(__half2*)((__half*)C + (size_t)m * ldc + n) =
                    __floats2half2_rn(acc[mf][nf][0], acc[mf][nf][1]);
                *(__half2*)((__half*)C + (size_t)(m + 8) * ldc + n) =
                    __floats2half2_rn(acc[mf][nf][2], acc[mf][nf][3]);
            } else {
                *(float2*)((float*)C + (size_t)m * ldc + n) =
                    make_float2(acc[mf][nf][0], acc[mf][nf][1]);
                *(float2*)((float*)C + (size_t)(m + 8) * ldc + n) =
                    make_float2(acc[mf][nf][2], acc[mf][nf][3]);
            }
        }
    }
}

// ============================================================================
// Exact fp32 delta_lr: dlr[t,k] = x[t,:]·W_in[k,:]
// ============================================================================
__global__ __launch_bounds__(256) void dlr_kernel(
    const float* __restrict__ x, const float* __restrict__ W_in)
{
    __shared__ float sx[64][36];
    __shared__ float sw[64][65];
    const int tid = threadIdx.x;
    const int k = tid & 63;
    const int tg = tid >> 6;
    const int t0 = blockIdx.x * 32;

    float acc[8];
    #pragma unroll
    for (int i = 0; i < 8; i++) acc[i] = 0.f;

    for (int kc = 0; kc < 16; kc++) {
        #pragma unroll
        for (int j = 0; j < 2; j++) {
            const int q = tid * 2 + j;
            const int t = q >> 4, c = q & 15;
            float4 v = *(const float4*)(x + (size_t)(t0 + t) * KDIM + kc * 64 + c * 4);
            sx[c * 4 + 0][t] = v.x; sx[c * 4 + 1][t] = v.y;
            sx[c * 4 + 2][t] = v.z; sx[c * 4 + 3][t] = v.w;
        }
        #pragma unroll
        for (int j = 0; j < 4; j++) {
            const int q = tid * 4 + j;
            const int k2 = q >> 4, c = q & 15;
            float4 v = *(const float4*)(W_in + (size_t)k2 * KDIM + kc * 64 + c * 4);
            sw[c * 4 + 0][k2] = v.x; sw[c * 4 + 1][k2] = v.y;
            sw[c * 4 + 2][k2] = v.z; sw[c * 4 + 3][k2] = v.w;
        }
        __syncthreads();
        #pragma unroll 16
        for (int kk = 0; kk < 64; kk++) {
            const float w = sw[kk][k];
            #pragma unroll
            for (int i = 0; i < 8; i++)
                acc[i] = fmaf(sx[kk][tg * 8 + i], w, acc[i]);
        }
        __syncthreads();
    }
    #pragma unroll
    for (int i = 0; i < 8; i++)
        g_dlr[(size_t)(t0 + tg * 8 + i) * DTR + k] = acc[i];
}

// ============================================================================
// delta[t,d] = softplus(g_dlr[t,:] · W_delta[d,:])
// ============================================================================
__global__ __launch_bounds__(128) void delta_kernel(const float* __restrict__ W_delta)
{
    __shared__ float s_dl[8][64];
    __shared__ float s_wT[64][129];
    const int tid = threadIdx.x;
    const int t0 = blockIdx.x * 8;
    const int d0 = blockIdx.y * 128;

    for (int i = tid; i < 8 * 64; i += 128) {
        int t = i >> 6, kk = i & 63;
        s_dl[t][kk] = g_dlr[(size_t)(t0 + t) * DTR + kk];
    }
    for (int i = tid; i < 128 * 64; i += 128) {
        int d = i >> 6, kk = i & 63;
        s_wT[kk][d] = W_delta[(size_t)(d0 + d) * DTR + kk];
    }
    __syncthreads();

    float accv[8];
    #pragma unroll
    for (int t = 0; t < 8; t++) accv[t] = 0.f;
    #pragma unroll 8
    for (int kk = 0; kk < 64; kk++) {
        float w = s_wT[kk][tid];
        #pragma unroll
        for (int t = 0; t < 8; t++) accv[t] = fmaf(s_dl[t][kk], w, accv[t]);
    }
    #pragma unroll
    for (int t = 0; t < 8; t++) {
        float z = accv[t];
        float sp = fmaxf(z, 0.f) + log1pf(__expf(-fabsf(z)));
        g_delta[(size_t)(t0 + t) * DI + d0 + tid] = sp;
    }
}

// ============================================================================
// Selective scan v2: cp.async smem-staged, 32-step chunks, 4-stage ring.
// Reads the compact g_bch buffer (row = [B 16384 | C 16384] halfs).
// ============================================================================
#define SC_T      32
#define SC_NCH    (L_SEQ / SC_T)
#define SC_BBYTES (SC_T * 256)
#define SC_DBYTES (SC_T * 32)
#define SC_B_OFF  0
#define SC_C_OFF  SC_BBYTES
#define SC_D_OFF  (2 * SC_BBYTES)
#define SC_X_OFF  (2 * SC_BBYTES + SC_DBYTES)
#define SC_STAGE  (2 * SC_BBYTES + 2 * SC_DBYTES)
#define SC_NSTAGE 4
#define SMEM_SCAN_TOTAL (SC_NSTAGE * SC_STAGE)

__global__ __launch_bounds__(128) void scan_kernel(
    const float* __restrict__ x, const float* __restrict__ A_log,
    const float* __restrict__ Dv)
{
    extern __shared__ char smem[];
    const uint32_t sbase = smem_u32(smem);
    const int tid = threadIdx.x;
    const int blk = blockIdx.x;
    const int lc = tid >> 4, s = tid & 15;
    const int d = blk * 8 + lc;

    const float a = -expf(A_log[d * DS + s]);
    const float Dd = Dv[d];

    const char* gB = (const char*)(g_bch + (size_t)blk * 128);
    const char* gC = (const char*)(g_bch + (size_t)DI * DS + (size_t)blk * 128);
    const char* gD = (const char*)(g_delta + (size_t)blk * 8);
    const char* gX = (const char*)(x + (size_t)blk * 8);

    auto issue = [&](int ch) {
        if (ch < SC_NCH) {
            const uint32_t soff = sbase + (ch & 3) * SC_STAGE;
            const size_t t0 = (size_t)ch * SC_T;
            #pragma unroll
            for (int j = 0; j < 4; j++) {
                const int q = tid * 4 + j;
                const int st = q >> 4, off = (q & 15) * 16;
                cp_async16(soff + SC_B_OFF + st * 256 + off,
                           gB + (t0 + st) * (BCW * 2) + off);
                cp_async16(soff + SC_C_OFF + st * 256 + off,
                           gC + (t0 + st) * (BCW * 2) + off);
            }
            {
                const int q = tid & 63;
                const int st = q >> 1, off = (q & 1) * 16;
                if (tid < 64)
                    cp_async16(soff + SC_D_OFF + st * 32 + off,
                               gD + (t0 + st) * (DI * 4) + off);
                else
                    cp_async16(soff + SC_X_OFF + st * 32 + off,
                               gX + (t0 + st) * (DI * 4) + off);
            }
        }
        CP_COMMIT();
    };

    issue(0); issue(1); issue(2);

    float h = 0.f;
    #pragma unroll 1
    for (int ch = 0; ch < SC_NCH; ch++) {
        CP_WAIT(2);
        __syncthreads();
        issue(ch + 3);

        const uint32_t so = (ch & 3) * SC_STAGE;
        const __half* sB = (const __half*)(smem + so + SC_B_OFF);
        const __half* sC = (const __half*)(smem + so + SC_C_OFF);
        const float* sD  = (const float*)(smem + so + SC_D_OFF);
        const float* sX  = (const float*)(smem + so + SC_X_OFF);
        const int tbase = ch * SC_T;

        #pragma unroll 8
        for (int st = 0; st < SC_T; st++) {
            const float Bv = __half2float(sB[st * 128 + tid]);
            const float Cv = __half2float(sC[st * 128 + tid]);
            const float dt = sD[st * 8 + lc];
            const float xt = sX[st * 8 + lc];
            h = fmaf(__expf(dt * a), h, dt * xt * Bv);
            float yv = h * Cv;
            yv += __shfl_xor_sync(0xffffffffu, yv, 1);
            yv += __shfl_xor_sync(0xffffffffu, yv, 2);
            yv += __shfl_xor_sync(0xffffffffu, yv, 4);
            yv += __shfl_xor_sync(0xffffffffu, yv, 8);
            if (s == 0)
                g_yf[(size_t)(tbase + st) * DI + d] =
                    __float2half_rn(fmaf(xt, Dd, yv));
        }
    }
}

// ============================================================================
// Launch
// ============================================================================
extern "C" void kernel_launch(void* const* d_in, const int* in_sizes, int n_in,
                              void* d_out, int out_size)
{
    const float* x       = (const float*)d_in[0];
    const float* W_in    = (const float*)d_in[1];
    const float* W_delta = (const float*)d_in[2];
    const float* A_log   = (const float*)d_in[3];
    const float* Dv      = (const float*)d_in[4];
    const float* W_out   = (const float*)d_in[5];
    float* out = (float*)d_out;

    __half *bch, *xf, *wf, *wof, *yf;
    cudaGetSymbolAddress((void**)&bch, g_bch);
    cudaGetSymbolAddress((void**)&xf, g_xf);
    cudaGetSymbolAddress((void**)&wf, g_wf);
    cudaGetSymbolAddress((void**)&wof, g_wof);
    cudaGetSymbolAddress((void**)&yf, g_yf);

    cudaFuncSetAttribute(gemm_f16<__half>, cudaFuncAttributeMaxDynamicSharedMemorySize,
                         SMEM_F16_TOTAL);
    cudaFuncSetAttribute(gemm_f16<float>, cudaFuncAttributeMaxDynamicSharedMemorySize,
                         SMEM_F16_TOTAL);
    cudaFuncSetAttribute(scan_kernel, cudaFuncAttributeMaxDynamicSharedMemorySize,
                         SMEM_SCAN_TOTAL);

    // 1) conversions (W_in: skip the 64 delta rows -> compact 32768-row weight)
    {
        size_t nx = (size_t)L_SEQ * DM;
        cvt16_kernel<<<(unsigned)((nx / 4 + 255) / 256), 256>>>(x, xf, nx);
        size_t nw = (size_t)BCW * DM;
        cvt16_kernel<<<(unsigned)((nw / 4 + 255) / 256), 256>>>(W_in + (size_t)DTR * DM, wf, nw);
        size_t nwo = (size_t)DM * DI;
        cvt16_kernel<<<(unsigned)((nwo / 4 + 255) / 256), 256>>>(W_out, wof, nwo);
    }
    // 2) B/C = x @ W_in[64:]^T  -> compact fp16 buffer (exact 256 n-tiles)
    {
        dim3 grid(L_SEQ / 128, BCW / 128);    // 16 x 256
        gemm_f16<__half><<<grid, 512, SMEM_F16_TOTAL>>>(xf, wf, bch, BCW);
    }
    // 3) exact fp32 delta_lr
    dlr_kernel<<<L_SEQ / 32, 256>>>(x, W_in);
    // 4) delta
    {
        dim3 grid(L_SEQ / 8, DI / 128);
        delta_kernel<<<grid, 128>>>(W_delta);
    }
    // 5) scan v2 (smem-staged)
    scan_kernel<<<128, 128, SMEM_SCAN_TOTAL>>>(x, A_log, Dv);
    // 6) out = y @ W_out^T  -> f32 output
    {
        dim3 grid(L_SEQ / 128, DM / 128);
        gemm_f16<float><<<grid, 512, SMEM_F16_TOTAL>>>(yf, wof, out, DM);
    }
}

// round 14
// speedup vs baseline: 1.1342x; 1.0471x over previous
#include <cuda_runtime.h>
#include <cuda_fp16.h>
#include <math.h>
#include <stdint.h>

// Problem constants
#define L_SEQ   2048
#define DM      1024
#define DI      1024
#define DTR     64
#define DS      16
#define PROJ    (DTR + 2 * DI * DS)   // 32832
#define BCW     32768                 // compact B/C width = 256 * 128
#define KDIM    1024

// -------- scratch (static device globals; no allocation) --------
__device__ __half g_bch[(size_t)L_SEQ * BCW];       // [B | C] per row, fp16
__device__ float  g_dlr[(size_t)L_SEQ * DTR];       // exact fp32 delta_lr
__device__ float  g_delta[(size_t)L_SEQ * DI];
__device__ __half g_xf[(size_t)L_SEQ * DM];
__device__ __half g_wf[(size_t)BCW * DM];           // W_in rows 64..32831
__device__ __half g_wof[(size_t)DM * DI];
__device__ __half g_yf[(size_t)L_SEQ * DI];
// two-pass scan intermediates: 16 chunks x 16384 (d,s) lanes
#define NCHK 16
#define CHK  (L_SEQ / NCHK)          // 128
__device__ float g_hp[NCHK * 16384];
__device__ float g_ap[NCHK * 16384];
__device__ float g_hin[NCHK * 16384];

// ============================================================================
// helpers
// ============================================================================
__device__ __forceinline__ uint32_t smem_u32(const void* p) {
    uint32_t a;
    asm("{ .reg .u64 t; cvta.to.shared.u64 t, %1; cvt.u32.u64 %0, t; }" : "=r"(a) : "l"(p));
    return a;
}
__device__ __forceinline__ uint32_t swz128(uint32_t o) { return o ^ ((o >> 3) & 0x70); }

__device__ __forceinline__ void cp_async16(uint32_t dst, const void* src) {
    asm volatile("cp.async.cg.shared.global [%0], [%1], 16;" :: "r"(dst), "l"(src));
}
#define CP_COMMIT() asm volatile("cp.async.commit_group;" ::: "memory")
#define CP_WAIT(n)  asm volatile("cp.async.wait_group %0;" :: "n"(n) : "memory")

__device__ __forceinline__ void ldsm4(uint32_t* r, uint32_t addr) {
    asm volatile("ldmatrix.sync.aligned.m8n8.x4.shared.b16 {%0,%1,%2,%3}, [%4];"
        : "=r"(r[0]), "=r"(r[1]), "=r"(r[2]), "=r"(r[3]) : "r"(addr));
}
__device__ __forceinline__ void mma_f16(float* d, const uint32_t* a, const uint32_t* b) {
    asm volatile(
        "mma.sync.aligned.m16n8k16.row.col.f32.f16.f16.f32 "
        "{%0,%1,%2,%3}, {%4,%5,%6,%7}, {%8,%9}, {%0,%1,%2,%3};"
        : "+f"(d[0]), "+f"(d[1]), "+f"(d[2]), "+f"(d[3])
        : "r"(a[0]), "r"(a[1]), "r"(a[2]), "r"(a[3]), "r"(b[0]), "r"(b[1]));
}

// ============================================================================
// Fused fp32 -> fp16 conversion for x, W_in[64:], W_out (one launch)
// ============================================================================
#define NX4   ((size_t)L_SEQ * DM / 4)
#define NW4   ((size_t)BCW * DM / 4)
#define NWO4  ((size_t)DM * DI / 4)
#define NALL4 (NX4 + NW4 + NWO4)

__global__ __launch_bounds__(256) void cvt_all_kernel(
    const float* __restrict__ x, const float* __restrict__ W_in,
    const float* __restrict__ W_out)
{
    size_t q = (size_t)blockIdx.x * 256 + threadIdx.x;
    if (q >= NALL4) return;
    const float* src;
    __half* dst;
    size_t i;
    if (q < NX4) { i = q * 4; src = x; dst = g_xf; }
    else if (q < NX4 + NW4) { i = (q - NX4) * 4; src = W_in + (size_t)DTR * DM; dst = g_wf; }
    else { i = (q - NX4 - NW4) * 4; src = W_out; dst = g_wof; }
    float4 v = *(const float4*)(src + i);
    *(__half2*)(dst + i)     = __floats2half2_rn(v.x, v.y);
    *(__half2*)(dst + i + 2) = __floats2half2_rn(v.z, v.w);
}

// ============================================================================
// FP16 GEMM v4 (unchanged from R13): CTA 128x128, BK=64, 512 thr, 2 CTAs/SM,
// per-warp ks rotation, 3-stage cp.async pipeline, guard-free epilogue.
// ============================================================================
#define F_ATILE  16384
#define F_STAGE  32768
#define F_NSTAGE 3
#define SMEM_F16_TOTAL (F_NSTAGE * F_STAGE)   // 96 KB
#define F_NKC    (KDIM / 64)        // 16

template<typename OT>
__global__ __launch_bounds__(512, 2) void gemm_f16(
    const __half* __restrict__ A, const __half* __restrict__ B,
    OT* __restrict__ C, int ldc)
{
    extern __shared__ char smem[];
    const uint32_t sbase = smem_u32(smem);
    const int tid = threadIdx.x;
    const int wid = tid >> 5, lane = tid & 31;
    const int wm = wid & 3, wn = wid >> 2;

    const int m0 = blockIdx.x * 128;
    const int n0 = blockIdx.y * 128;

    float acc[2][4][4];
    #pragma unroll
    for (int i = 0; i < 2; i++)
        #pragma unroll
        for (int j = 0; j < 4; j++)
            #pragma unroll
            for (int q = 0; q < 4; q++) acc[i][j][q] = 0.f;

    auto issue = [&](int kc) {
        if (kc < F_NKC) {
            const uint32_t soff = sbase + (kc % F_NSTAGE) * F_STAGE;
            #pragma unroll
            for (int j = 0; j < 2; j++) {
                const int q = tid * 2 + j;
                const int row = q >> 3, c = q & 7;
                const uint32_t so = swz128((uint32_t)(row * 128 + c * 16));
                const size_t ga = (size_t)(m0 + row) * KDIM + (size_t)kc * 64 + c * 8;
                const size_t gb = (size_t)(n0 + row) * KDIM + (size_t)kc * 64 + c * 8;
                cp_async16(soff + so, A + ga);
                cp_async16(soff + F_ATILE + so, B + gb);
            }
        }
        CP_COMMIT();
    };

    const int rb_base = wn * 32 + ((lane >> 4) << 3) + (lane & 7);
    const int cb_half = (lane >> 3) & 1;
    const int ra_base = wm * 32 + (lane & 15);
    const int ca_half = lane >> 4;
    const int ksr = wn;

    issue(0);
    issue(1);

    #pragma unroll 1
    for (int kc = 0; kc < F_NKC; kc++) {
        if (kc + 1 < F_NKC) CP_WAIT(1); else CP_WAIT(0);
        __syncthreads();
        issue(kc + 2);

        const uint32_t sA = sbase + (kc % F_NSTAGE) * F_STAGE;

        #pragma unroll
        for (int kss = 0; kss < 4; kss++) {
            const int ks = (kss + ksr) & 3;
            uint32_t bf[4][2];
            #pragma unroll
            for (int p = 0; p < 2; p++) {
                const int rowb = rb_base + p * 16;
                const int chb  = ks * 2 + cb_half;
                ldsm4(&bf[p * 2][0],
                      sA + F_ATILE + swz128((uint32_t)(rowb * 128 + chb * 16)));
            }
            #pragma unroll
            for (int mf = 0; mf < 2; mf++) {
                const int rowa = ra_base + mf * 16;
                const int cha  = ks * 2 + ca_half;
                uint32_t af[4];
                ldsm4(af, sA + swz128((uint32_t)(rowa * 128 + cha * 16)));
                #pragma unroll
                for (int nf = 0; nf < 4; nf++) mma_f16(acc[mf][nf], af, bf[nf]);
            }
        }
    }

    const int g = lane >> 2, t4 = lane & 3;
    #pragma unroll
    for (int mf = 0; mf < 2; mf++) {
        #pragma unroll
        for (int nf = 0; nf < 4; nf++) {
            const int m = m0 + wm * 32 + mf * 16 + g;
            const int n = n0 + wn * 32 + nf * 8 + t4 * 2;
            if constexpr (sizeof(OT) == 2) {
                *(__half2*)((__half*)C + (size_t)m * ldc + n) =
                    __floats2half2_rn(acc[mf][nf][0], acc[mf][nf][1]);
                *(__half2*)((__half*)C + (size_t)(m + 8) * ldc + n) =
                    __floats2half2_rn(acc[mf][nf][2], acc[mf][nf][3]);
            } else {
                *(float2*)((float*)C + (size_t)m * ldc + n) =
                    make_float2(acc[mf][nf][0], acc[mf][nf][1]);
                *(float2*)((float*)C + (size_t)(m + 8) * ldc + n) =
                    make_float2(acc[mf][nf][2], acc[mf][nf][3]);
            }
        }
    }
}

// ============================================================================
// Exact fp32 delta_lr: dlr[t,k] = x[t,:]·W_in[k,:]  — 128 CTAs (16 t-rows each)
// ============================================================================
__global__ __launch_bounds__(256) void dlr_kernel(
    const float* __restrict__ x, const float* __restrict__ W_in)
{
    __shared__ float sx[64][17];      // [kk][t], padded
    __shared__ float sw[64][65];      // [kk][k], padded
    const int tid = threadIdx.x;
    const int k = tid & 63;
    const int tg = tid >> 6;          // 0..3, 4 t-rows each
    const int t0 = blockIdx.x * 16;

    float acc[4];
    #pragma unroll
    for (int i = 0; i < 4; i++) acc[i] = 0.f;

    for (int kc = 0; kc < 16; kc++) {
        {   // x tile: 16 t x 64 kk = 256 float4, 1 per thread
            const int t = tid >> 4, c = tid & 15;
            float4 v = *(const float4*)(x + (size_t)(t0 + t) * KDIM + kc * 64 + c * 4);
            sx[c * 4 + 0][t] = v.x; sx[c * 4 + 1][t] = v.y;
            sx[c * 4 + 2][t] = v.z; sx[c * 4 + 3][t] = v.w;
        }
        #pragma unroll
        for (int j = 0; j < 4; j++) {   // W tile: 64 k x 64 kk
            const int q = tid * 4 + j;
            const int k2 = q >> 4, c = q & 15;
            float4 v = *(const float4*)(W_in + (size_t)k2 * KDIM + kc * 64 + c * 4);
            sw[c * 4 + 0][k2] = v.x; sw[c * 4 + 1][k2] = v.y;
            sw[c * 4 + 2][k2] = v.z; sw[c * 4 + 3][k2] = v.w;
        }
        __syncthreads();
        #pragma unroll 16
        for (int kk = 0; kk < 64; kk++) {
            const float w = sw[kk][k];
            #pragma unroll
            for (int i = 0; i < 4; i++)
                acc[i] = fmaf(sx[kk][tg * 4 + i], w, acc[i]);
        }
        __syncthreads();
    }
    #pragma unroll
    for (int i = 0; i < 4; i++)
        g_dlr[(size_t)(t0 + tg * 4 + i) * DTR + k] = acc[i];
}

// ============================================================================
// delta[t,d] = softplus(g_dlr[t,:] · W_delta[d,:])
// ============================================================================
__global__ __launch_bounds__(128) void delta_kernel(const float* __restrict__ W_delta)
{
    __shared__ float s_dl[8][64];
    __shared__ float s_wT[64][129];
    const int tid = threadIdx.x;
    const int t0 = blockIdx.x * 8;
    const int d0 = blockIdx.y * 128;

    for (int i = tid; i < 8 * 64; i += 128) {
        int t = i >> 6, kk = i & 63;
        s_dl[t][kk] = g_dlr[(size_t)(t0 + t) * DTR + kk];
    }
    for (int i = tid; i < 128 * 64; i += 128) {
        int d = i >> 6, kk = i & 63;
        s_wT[kk][d] = W_delta[(size_t)(d0 + d) * DTR + kk];
    }
    __syncthreads();

    float accv[8];
    #pragma unroll
    for (int t = 0; t < 8; t++) accv[t] = 0.f;
    #pragma unroll 8
    for (int kk = 0; kk < 64; kk++) {
        float w = s_wT[kk][tid];
        #pragma unroll
        for (int t = 0; t < 8; t++) accv[t] = fmaf(s_dl[t][kk], w, accv[t]);
    }
    #pragma unroll
    for (int t = 0; t < 8; t++) {
        float z = accv[t];
        float sp = fmaxf(z, 0.f) + log1pf(__expf(-fabsf(z)));
        g_delta[(size_t)(t0 + t) * DI + d0 + tid] = sp;
    }
}

// ============================================================================
// Two-pass chunked scan. Linear recurrence h' = a_t h + b_t composes over a
// chunk as h_end = (prod a_t)·h_start + h_chunk(0), with
// prod exp(dt·a) = exp(a·sum dt).
// Pass A: per (d,s,chunk): h_part (from 0) and a_prod.     grid (128, 16)
// Combine: chain 16 chunk states per (d,s).                grid 128
// Pass B: replay chunk with correct h_start, emit y.       grid (128, 16)
// ============================================================================
#define SC_T      32
#define SC_BBYTES (SC_T * 256)               // 8192
#define SC_DBYTES (SC_T * 32)                // 1024
// pass A stage: B + D + X
#define A_D_OFF   SC_BBYTES
#define A_X_OFF   (SC_BBYTES + SC_DBYTES)
#define A_STAGE   (SC_BBYTES + 2 * SC_DBYTES)      // 10240
#define SMEM_SCANA_TOTAL (4 * A_STAGE)             // 40960
// pass B stage: B + C + D + X
#define B_C_OFF   SC_BBYTES
#define B_D_OFF   (2 * SC_BBYTES)
#define B_X_OFF   (2 * SC_BBYTES + SC_DBYTES)
#define B_STAGE   (2 * SC_BBYTES + 2 * SC_DBYTES)  // 18432
#define SMEM_SCANB_TOTAL (4 * B_STAGE)             // 73728

__global__ __launch_bounds__(128) void scan_a_kernel(
    const float* __restrict__ x, const float* __restrict__ A_log)
{
    extern __shared__ char smem[];
    const uint32_t sbase = smem_u32(smem);
    const int tid = threadIdx.x;
    const int blk = blockIdx.x;
    const int c   = blockIdx.y;
    const int lc = tid >> 4, s = tid & 15;
    const int d = blk * 8 + lc;
    const float a = -expf(A_log[d * DS + s]);
    const size_t tb = (size_t)c * CHK;

    const char* gB = (const char*)(g_bch + (size_t)blk * 128);
    const char* gD = (const char*)(g_delta + (size_t)blk * 8);
    const char* gX = (const char*)(x + (size_t)blk * 8);

    #pragma unroll
    for (int st = 0; st < 4; st++) {
        const uint32_t soff = sbase + st * A_STAGE;
        const size_t t0 = tb + (size_t)st * SC_T;
        #pragma unroll
        for (int j = 0; j < 4; j++) {
            const int q = tid * 4 + j;
            const int stp = q >> 4, off = (q & 15) * 16;
            cp_async16(soff + stp * 256 + off, gB + (t0 + stp) * (BCW * 2) + off);
        }
        {
            const int q = tid & 63;
            const int stp = q >> 1, off = (q & 1) * 16;
            if (tid < 64)
                cp_async16(soff + A_D_OFF + stp * 32 + off, gD + (t0 + stp) * (DI * 4) + off);
            else
                cp_async16(soff + A_X_OFF + stp * 32 + off, gX + (t0 + stp) * (DI * 4) + off);
        }
        CP_COMMIT();
    }

    float h = 0.f, sdt = 0.f;
    #pragma unroll
    for (int st = 0; st < 4; st++) {
        switch (st) {
            case 0: CP_WAIT(3); break;
            case 1: CP_WAIT(2); break;
            case 2: CP_WAIT(1); break;
            default: CP_WAIT(0); break;
        }
        __syncthreads();
        const uint32_t so = st * A_STAGE;
        const __half* sB = (const __half*)(smem + so);
        const float* sD  = (const float*)(smem + so + A_D_OFF);
        const float* sX  = (const float*)(smem + so + A_X_OFF);
        #pragma unroll 8
        for (int stp = 0; stp < SC_T; stp++) {
            const float Bv = __half2float(sB[stp * 128 + tid]);
            const float dt = sD[stp * 8 + lc];
            const float xt = sX[stp * 8 + lc];
            h = fmaf(__expf(dt * a), h, dt * xt * Bv);
            sdt += dt;
        }
    }
    const int i = blk * 128 + tid;
    g_hp[c * 16384 + i] = h;
    g_ap[c * 16384 + i] = __expf(a * sdt);
}

__global__ __launch_bounds__(128) void scan_combine_kernel()
{
    const int i = blockIdx.x * 128 + threadIdx.x;
    float hp[NCHK], ap[NCHK];
    #pragma unroll
    for (int cc = 0; cc < NCHK; cc++) {
        hp[cc] = g_hp[cc * 16384 + i];
        ap[cc] = g_ap[cc * 16384 + i];
    }
    float hin = 0.f;
    #pragma unroll
    for (int cc = 0; cc < NCHK; cc++) {
        g_hin[cc * 16384 + i] = hin;
        hin = fmaf(ap[cc], hin, hp[cc]);
    }
}

__global__ __launch_bounds__(128) void scan_b_kernel(
    const float* __restrict__ x, const float* __restrict__ A_log,
    const float* __restrict__ Dv)
{
    extern __shared__ char smem[];
    const uint32_t sbase = smem_u32(smem);
    const int tid = threadIdx.x;
    const int blk = blockIdx.x;
    const int c   = blockIdx.y;
    const int lc = tid >> 4, s = tid & 15;
    const int d = blk * 8 + lc;
    const float a = -expf(A_log[d * DS + s]);
    const float Dd = Dv[d];
    const size_t tb = (size_t)c * CHK;

    const char* gB = (const char*)(g_bch + (size_t)blk * 128);
    const char* gC = (const char*)(g_bch + (size_t)DI * DS + (size_t)blk * 128);
    const char* gD = (const char*)(g_delta + (size_t)blk * 8);
    const char* gX = (const char*)(x + (size_t)blk * 8);

    #pragma unroll
    for (int st = 0; st < 4; st++) {
        const uint32_t soff = sbase + st * B_STAGE;
        const size_t t0 = tb + (size_t)st * SC_T;
        #pragma unroll
        for (int j = 0; j < 4; j++) {
            const int q = tid * 4 + j;
            const int stp = q >> 4, off = (q & 15) * 16;
            cp_async16(soff + stp * 256 + off, gB + (t0 + stp) * (BCW * 2) + off);
            cp_async16(soff + B_C_OFF + stp * 256 + off, gC + (t0 + stp) * (BCW * 2) + off);
        }
        {
            const int q = tid & 63;
            const int stp = q >> 1, off = (q & 1) * 16;
            if (tid < 64)
                cp_async16(soff + B_D_OFF + stp * 32 + off, gD + (t0 + stp) * (DI * 4) + off);
            else
                cp_async16(soff + B_X_OFF + stp * 32 + off, gX + (t0 + stp) * (DI * 4) + off);
        }
        CP_COMMIT();
    }

    float h = g_hin[c * 16384 + blk * 128 + tid];
    #pragma unroll
    for (int st = 0; st < 4; st++) {
        switch (st) {
            case 0: CP_WAIT(3); break;
            case 1: CP_WAIT(2); break;
            case 2: CP_WAIT(1); break;
            default: CP_WAIT(0); break;
        }
        __syncthreads();
        const uint32_t so = st * B_STAGE;
        const __half* sB = (const __half*)(smem + so);
        const __half* sC = (const __half*)(smem + so + B_C_OFF);
        const float* sD  = (const float*)(smem + so + B_D_OFF);
        const float* sX  = (const float*)(smem + so + B_X_OFF);
        const int tbase = (int)tb + st * SC_T;
        #pragma unroll 8
        for (int stp = 0; stp < SC_T; stp++) {
            const float Bv = __half2float(sB[stp * 128 + tid]);
            const float Cv = __half2float(sC[stp * 128 + tid]);
            const float dt = sD[stp * 8 + lc];
            const float xt = sX[stp * 8 + lc];
            h = fmaf(__expf(dt * a), h, dt * xt * Bv);
            float yv = h * Cv;
            yv += __shfl_xor_sync(0xffffffffu, yv, 1);
            yv += __shfl_xor_sync(0xffffffffu, yv, 2);
            yv += __shfl_xor_sync(0xffffffffu, yv, 4);
            yv += __shfl_xor_sync(0xffffffffu, yv, 8);
            if (s == 0)
                g_yf[(size_t)(tbase + stp) * DI + d] =
                    __float2half_rn(fmaf(xt, Dd, yv));
        }
    }
}

// ============================================================================
// Launch
// ============================================================================
extern "C" void kernel_launch(void* const* d_in, const int* in_sizes, int n_in,
                              void* d_out, int out_size)
{
    const float* x       = (const float*)d_in[0];
    const float* W_in    = (const float*)d_in[1];
    const float* W_delta = (const float*)d_in[2];
    const float* A_log   = (const float*)d_in[3];
    const float* Dv      = (const float*)d_in[4];
    const float* W_out   = (const float*)d_in[5];
    float* out = (float*)d_out;

    __half *bch, *xf, *wf, *wof, *yf;
    cudaGetSymbolAddress((void**)&bch, g_bch);
    cudaGetSymbolAddress((void**)&xf, g_xf);
    cudaGetSymbolAddress((void**)&wf, g_wf);
    cudaGetSymbolAddress((void**)&wof, g_wof);
    cudaGetSymbolAddress((void**)&yf, g_yf);

    cudaFuncSetAttribute(gemm_f16<__half>, cudaFuncAttributeMaxDynamicSharedMemorySize,
                         SMEM_F16_TOTAL);
    cudaFuncSetAttribute(gemm_f16<float>, cudaFuncAttributeMaxDynamicSharedMemorySize,
                         SMEM_F16_TOTAL);
    cudaFuncSetAttribute(scan_a_kernel, cudaFuncAttributeMaxDynamicSharedMemorySize,
                         SMEM_SCANA_TOTAL);
    cudaFuncSetAttribute(scan_b_kernel, cudaFuncAttributeMaxDynamicSharedMemorySize,
                         SMEM_SCANB_TOTAL);

    // 1) fused conversions (x, W_in[64:], W_out)
    cvt_all_kernel<<<(unsigned)((NALL4 + 255) / 256), 256>>>(x, W_in, W_out);
    // 2) B/C = x @ W_in[64:]^T  -> compact fp16 buffer
    {
        dim3 grid(L_SEQ / 128, BCW / 128);    // 16 x 256
        gemm_f16<__half><<<grid, 512, SMEM_F16_TOTAL>>>(xf, wf, bch, BCW);
    }
    // 3) exact fp32 delta_lr (128 CTAs)
    dlr_kernel<<<L_SEQ / 16, 256>>>(x, W_in);
    // 4) delta
    {
        dim3 grid(L_SEQ / 8, DI / 128);
        delta_kernel<<<grid, 128>>>(W_delta);
    }
    // 5) two-pass chunked scan
    {
        dim3 ga(128, NCHK);
        scan_a_kernel<<<ga, 128, SMEM_SCANA_TOTAL>>>(x, A_log);
        scan_combine_kernel<<<128, 128>>>();
        scan_b_kernel<<<ga, 128, SMEM_SCANB_TOTAL>>>(x, A_log, Dv);
    }
    // 6) out = y @ W_out^T  -> f32 output
    {
        dim3 grid(L_SEQ / 128, DM / 128);
        gemm_f16<float><<<grid, 512, SMEM_F16_TOTAL>>>(yf, wof, out, DM);
    }
}

// round 15
// speedup vs baseline: 1.1562x; 1.0194x over previous
#include <cuda_runtime.h>
#include <cuda_fp16.h>
#include <math.h>
#include <stdint.h>

// Problem constants
#define L_SEQ   2048
#define DM      1024
#define DI      1024
#define DTR     64
#define DS      16
#define PROJ    (DTR + 2 * DI * DS)   // 32832
#define BCW     32768                 // compact B/C width = 256 * 128
#define KDIM    1024

// -------- scratch (static device globals; no allocation) --------
__device__ __half g_bch[(size_t)L_SEQ * BCW];       // [B | C] per row, fp16
__device__ float  g_dlr[(size_t)L_SEQ * DTR];       // exact fp32 delta_lr
__device__ float  g_delta[(size_t)L_SEQ * DI];
__device__ __half g_xf[(size_t)L_SEQ * DM];
__device__ __half g_wf[(size_t)BCW * DM];           // W_in rows 64..32831
__device__ __half g_wof[(size_t)DM * DI];
__device__ __half g_yf[(size_t)L_SEQ * DI];
// two-pass scan intermediates: 16 chunks x 16384 (d,s) lanes
#define NCHK 16
#define CHK  (L_SEQ / NCHK)          // 128
__device__ float g_hp[NCHK * 16384];
__device__ float g_ap[NCHK * 16384];
__device__ float g_hin[NCHK * 16384];

// ============================================================================
// helpers
// ============================================================================
__device__ __forceinline__ uint32_t smem_u32(const void* p) {
    uint32_t a;
    asm("{ .reg .u64 t; cvta.to.shared.u64 t, %1; cvt.u32.u64 %0, t; }" : "=r"(a) : "l"(p));
    return a;
}
__device__ __forceinline__ uint32_t swz128(uint32_t o) { return o ^ ((o >> 3) & 0x70); }

__device__ __forceinline__ void cp_async16(uint32_t dst, const void* src) {
    asm volatile("cp.async.cg.shared.global [%0], [%1], 16;" :: "r"(dst), "l"(src));
}
#define CP_COMMIT() asm volatile("cp.async.commit_group;" ::: "memory")
#define CP_WAIT(n)  asm volatile("cp.async.wait_group %0;" :: "n"(n) : "memory")

__device__ __forceinline__ void ldsm4(uint32_t* r, uint32_t addr) {
    asm volatile("ldmatrix.sync.aligned.m8n8.x4.shared.b16 {%0,%1,%2,%3}, [%4];"
        : "=r"(r[0]), "=r"(r[1]), "=r"(r[2]), "=r"(r[3]) : "r"(addr));
}
__device__ __forceinline__ void mma_f16(float* d, const uint32_t* a, const uint32_t* b) {
    asm volatile(
        "mma.sync.aligned.m16n8k16.row.col.f32.f16.f16.f32 "
        "{%0,%1,%2,%3}, {%4,%5,%6,%7}, {%8,%9}, {%0,%1,%2,%3};"
        : "+f"(d[0]), "+f"(d[1]), "+f"(d[2]), "+f"(d[3])
        : "r"(a[0]), "r"(a[1]), "r"(a[2]), "r"(a[3]), "r"(b[0]), "r"(b[1]));
}

// ============================================================================
// Fused fp32 -> fp16 conversion for x, W_in[64:], W_out (one launch)
// ============================================================================
#define NX4   ((size_t)L_SEQ * DM / 4)
#define NW4   ((size_t)BCW * DM / 4)
#define NWO4  ((size_t)DM * DI / 4)
#define NALL4 (NX4 + NW4 + NWO4)

__global__ __launch_bounds__(256) void cvt_all_kernel(
    const float* __restrict__ x, const float* __restrict__ W_in,
    const float* __restrict__ W_out)
{
    size_t q = (size_t)blockIdx.x * 256 + threadIdx.x;
    if (q >= NALL4) return;
    const float* src;
    __half* dst;
    size_t i;
    if (q < NX4) { i = q * 4; src = x; dst = g_xf; }
    else if (q < NX4 + NW4) { i = (q - NX4) * 4; src = W_in + (size_t)DTR * DM; dst = g_wf; }
    else { i = (q - NX4 - NW4) * 4; src = W_out; dst = g_wof; }
    float4 v = *(const float4*)(src + i);
    *(__half2*)(dst + i)     = __floats2half2_rn(v.x, v.y);
    *(__half2*)(dst + i + 2) = __floats2half2_rn(v.z, v.w);
}

// ============================================================================
// FP16 GEMM v4 (unchanged): CTA 128x128, BK=64, 512 thr, 2 CTAs/SM,
// per-warp ks rotation, 3-stage cp.async pipeline, guard-free epilogue.
// ============================================================================
#define F_ATILE  16384
#define F_STAGE  32768
#define F_NSTAGE 3
#define SMEM_F16_TOTAL (F_NSTAGE * F_STAGE)   // 96 KB
#define F_NKC    (KDIM / 64)        // 16

template<typename OT>
__global__ __launch_bounds__(512, 2) void gemm_f16(
    const __half* __restrict__ A, const __half* __restrict__ B,
    OT* __restrict__ C, int ldc)
{
    extern __shared__ char smem[];
    const uint32_t sbase = smem_u32(smem);
    const int tid = threadIdx.x;
    const int wid = tid >> 5, lane = tid & 31;
    const int wm = wid & 3, wn = wid >> 2;

    const int m0 = blockIdx.x * 128;
    const int n0 = blockIdx.y * 128;

    float acc[2][4][4];
    #pragma unroll
    for (int i = 0; i < 2; i++)
        #pragma unroll
        for (int j = 0; j < 4; j++)
            #pragma unroll
            for (int q = 0; q < 4; q++) acc[i][j][q] = 0.f;

    auto issue = [&](int kc) {
        if (kc < F_NKC) {
            const uint32_t soff = sbase + (kc % F_NSTAGE) * F_STAGE;
            #pragma unroll
            for (int j = 0; j < 2; j++) {
                const int q = tid * 2 + j;
                const int row = q >> 3, c = q & 7;
                const uint32_t so = swz128((uint32_t)(row * 128 + c * 16));
                const size_t ga = (size_t)(m0 + row) * KDIM + (size_t)kc * 64 + c * 8;
                const size_t gb = (size_t)(n0 + row) * KDIM + (size_t)kc * 64 + c * 8;
                cp_async16(soff + so, A + ga);
                cp_async16(soff + F_ATILE + so, B + gb);
            }
        }
        CP_COMMIT();
    };

    const int rb_base = wn * 32 + ((lane >> 4) << 3) + (lane & 7);
    const int cb_half = (lane >> 3) & 1;
    const int ra_base = wm * 32 + (lane & 15);
    const int ca_half = lane >> 4;
    const int ksr = wn;

    issue(0);
    issue(1);

    #pragma unroll 1
    for (int kc = 0; kc < F_NKC; kc++) {
        if (kc + 1 < F_NKC) CP_WAIT(1); else CP_WAIT(0);
        __syncthreads();
        issue(kc + 2);

        const uint32_t sA = sbase + (kc % F_NSTAGE) * F_STAGE;

        #pragma unroll
        for (int kss = 0; kss < 4; kss++) {
            const int ks = (kss + ksr) & 3;
            uint32_t bf[4][2];
            #pragma unroll
            for (int p = 0; p < 2; p++) {
                const int rowb = rb_base + p * 16;
                const int chb  = ks * 2 + cb_half;
                ldsm4(&bf[p * 2][0],
                      sA + F_ATILE + swz128((uint32_t)(rowb * 128 + chb * 16)));
            }
            #pragma unroll
            for (int mf = 0; mf < 2; mf++) {
                const int rowa = ra_base + mf * 16;
                const int cha  = ks * 2 + ca_half;
                uint32_t af[4];
                ldsm4(af, sA + swz128((uint32_t)(rowa * 128 + cha * 16)));
                #pragma unroll
                for (int nf = 0; nf < 4; nf++) mma_f16(acc[mf][nf], af, bf[nf]);
            }
        }
    }

    const int g = lane >> 2, t4 = lane & 3;
    #pragma unroll
    for (int mf = 0; mf < 2; mf++) {
        #pragma unroll
        for (int nf = 0; nf < 4; nf++) {
            const int m = m0 + wm * 32 + mf * 16 + g;
            const int n = n0 + wn * 32 + nf * 8 + t4 * 2;
            if constexpr (sizeof(OT) == 2) {
                *(__half2*)((__half*)C + (size_t)m * ldc + n) =
                    __floats2half2_rn(acc[mf][nf][0], acc[mf][nf][1]);
                *(__half2*)((__half*)C + (size_t)(m + 8) * ldc + n) =
                    __floats2half2_rn(acc[mf][nf][2], acc[mf][nf][3]);
            } else {
                *(float2*)((float*)C + (size_t)m * ldc + n) =
                    make_float2(acc[mf][nf][0], acc[mf][nf][1]);
                *(float2*)((float*)C + (size_t)(m + 8) * ldc + n) =
                    make_float2(acc[mf][nf][2], acc[mf][nf][3]);
            }
        }
    }
}

// ============================================================================
// Exact fp32 delta_lr: dlr[t,k] = x[t,:]·W_in[k,:]  — 128 CTAs (16 t-rows each)
// ============================================================================
__global__ __launch_bounds__(256) void dlr_kernel(
    const float* __restrict__ x, const float* __restrict__ W_in)
{
    __shared__ float sx[64][17];
    __shared__ float sw[64][65];
    const int tid = threadIdx.x;
    const int k = tid & 63;
    const int tg = tid >> 6;
    const int t0 = blockIdx.x * 16;

    float acc[4];
    #pragma unroll
    for (int i = 0; i < 4; i++) acc[i] = 0.f;

    for (int kc = 0; kc < 16; kc++) {
        {
            const int t = tid >> 4, c = tid & 15;
            float4 v = *(const float4*)(x + (size_t)(t0 + t) * KDIM + kc * 64 + c * 4);
            sx[c * 4 + 0][t] = v.x; sx[c * 4 + 1][t] = v.y;
            sx[c * 4 + 2][t] = v.z; sx[c * 4 + 3][t] = v.w;
        }
        #pragma unroll
        for (int j = 0; j < 4; j++) {
            const int q = tid * 4 + j;
            const int k2 = q >> 4, c = q & 15;
            float4 v = *(const float4*)(W_in + (size_t)k2 * KDIM + kc * 64 + c * 4);
            sw[c * 4 + 0][k2] = v.x; sw[c * 4 + 1][k2] = v.y;
            sw[c * 4 + 2][k2] = v.z; sw[c * 4 + 3][k2] = v.w;
        }
        __syncthreads();
        #pragma unroll 16
        for (int kk = 0; kk < 64; kk++) {
            const float w = sw[kk][k];
            #pragma unroll
            for (int i = 0; i < 4; i++)
                acc[i] = fmaf(sx[kk][tg * 4 + i], w, acc[i]);
        }
        __syncthreads();
    }
    #pragma unroll
    for (int i = 0; i < 4; i++)
        g_dlr[(size_t)(t0 + tg * 4 + i) * DTR + k] = acc[i];
}

// ============================================================================
// delta v2: delta[t,d] = softplus(g_dlr[t,:]·W_delta[d,:])
// 128 threads, t-tile 32, grid (64, 8). float4 dl (LDS.128 broadcast) +
// 4 scalar w per 4-kk step -> LDS:FMA = 0.28:1 (was ~1.1:1).
// ============================================================================
__global__ __launch_bounds__(128) void delta_kernel(const float* __restrict__ W_delta)
{
    __shared__ float s_dl[32][64];       // [t][kk], rows 256B-aligned for float4
    __shared__ float s_wT[64][129];      // [kk][d], padded
    const int tid = threadIdx.x;
    const int t0 = blockIdx.x * 32;
    const int d0 = blockIdx.y * 128;

    // load dlr tile: 32 t x 64 kk = 512 float4, 4 per thread
    #pragma unroll
    for (int j = 0; j < 4; j++) {
        const int q = tid * 4 + j;           // 0..511
        const int t = q >> 4, c = q & 15;
        float4 v = *(const float4*)(g_dlr + (size_t)(t0 + t) * DTR + c * 4);
        *(float4*)&s_dl[t][c * 4] = v;
    }
    // load W tile: 128 d x 64 kk = 2048 float4, 16 per thread (transpose)
    #pragma unroll
    for (int j = 0; j < 16; j++) {
        const int q = tid * 16 + j;          // 0..2047
        const int d = q >> 4, c = q & 15;
        float4 v = *(const float4*)(W_delta + (size_t)(d0 + d) * DTR + c * 4);
        s_wT[c * 4 + 0][d] = v.x; s_wT[c * 4 + 1][d] = v.y;
        s_wT[c * 4 + 2][d] = v.z; s_wT[c * 4 + 3][d] = v.w;
    }
    __syncthreads();

    float accv[32];
    #pragma unroll
    for (int t = 0; t < 32; t++) accv[t] = 0.f;

    #pragma unroll 4
    for (int k4 = 0; k4 < 16; k4++) {
        const float w0 = s_wT[k4 * 4 + 0][tid];
        const float w1 = s_wT[k4 * 4 + 1][tid];
        const float w2 = s_wT[k4 * 4 + 2][tid];
        const float w3 = s_wT[k4 * 4 + 3][tid];
        #pragma unroll
        for (int t = 0; t < 32; t++) {
            const float4 dl = *(const float4*)&s_dl[t][k4 * 4];
            float a = fmaf(dl.x, w0, accv[t]);
            a = fmaf(dl.y, w1, a);
            a = fmaf(dl.z, w2, a);
            accv[t] = fmaf(dl.w, w3, a);
        }
    }
    #pragma unroll
    for (int t = 0; t < 32; t++) {
        const float z = accv[t];
        const float sp = fmaxf(z, 0.f) + log1pf(__expf(-fabsf(z)));
        g_delta[(size_t)(t0 + t) * DI + d0 + tid] = sp;
    }
}

// ============================================================================
// Two-pass chunked scan (unchanged from R14).
// ============================================================================
#define SC_T      32
#define SC_BBYTES (SC_T * 256)
#define SC_DBYTES (SC_T * 32)
#define A_D_OFF   SC_BBYTES
#define A_X_OFF   (SC_BBYTES + SC_DBYTES)
#define A_STAGE   (SC_BBYTES + 2 * SC_DBYTES)
#define SMEM_SCANA_TOTAL (4 * A_STAGE)
#define B_C_OFF   SC_BBYTES
#define B_D_OFF   (2 * SC_BBYTES)
#define B_X_OFF   (2 * SC_BBYTES + SC_DBYTES)
#define B_STAGE   (2 * SC_BBYTES + 2 * SC_DBYTES)
#define SMEM_SCANB_TOTAL (4 * B_STAGE)

__global__ __launch_bounds__(128) void scan_a_kernel(
    const float* __restrict__ x, const float* __restrict__ A_log)
{
    extern __shared__ char smem[];
    const uint32_t sbase = smem_u32(smem);
    const int tid = threadIdx.x;
    const int blk = blockIdx.x;
    const int c   = blockIdx.y;
    const int lc = tid >> 4, s = tid & 15;
    const int d = blk * 8 + lc;
    const float a = -expf(A_log[d * DS + s]);
    const size_t tb = (size_t)c * CHK;

    const char* gB = (const char*)(g_bch + (size_t)blk * 128);
    const char* gD = (const char*)(g_delta + (size_t)blk * 8);
    const char* gX = (const char*)(x + (size_t)blk * 8);

    #pragma unroll
    for (int st = 0; st < 4; st++) {
        const uint32_t soff = sbase + st * A_STAGE;
        const size_t t0 = tb + (size_t)st * SC_T;
        #pragma unroll
        for (int j = 0; j < 4; j++) {
            const int q = tid * 4 + j;
            const int stp = q >> 4, off = (q & 15) * 16;
            cp_async16(soff + stp * 256 + off, gB + (t0 + stp) * (BCW * 2) + off);
        }
        {
            const int q = tid & 63;
            const int stp = q >> 1, off = (q & 1) * 16;
            if (tid < 64)
                cp_async16(soff + A_D_OFF + stp * 32 + off, gD + (t0 + stp) * (DI * 4) + off);
            else
                cp_async16(soff + A_X_OFF + stp * 32 + off, gX + (t0 + stp) * (DI * 4) + off);
        }
        CP_COMMIT();
    }

    float h = 0.f, sdt = 0.f;
    #pragma unroll
    for (int st = 0; st < 4; st++) {
        switch (st) {
            case 0: CP_WAIT(3); break;
            case 1: CP_WAIT(2); break;
            case 2: CP_WAIT(1); break;
            default: CP_WAIT(0); break;
        }
        __syncthreads();
        const uint32_t so = st * A_STAGE;
        const __half* sB = (const __half*)(smem + so);
        const float* sD  = (const float*)(smem + so + A_D_OFF);
        const float* sX  = (const float*)(smem + so + A_X_OFF);
        #pragma unroll 8
        for (int stp = 0; stp < SC_T; stp++) {
            const float Bv = __half2float(sB[stp * 128 + tid]);
            const float dt = sD[stp * 8 + lc];
            const float xt = sX[stp * 8 + lc];
            h = fmaf(__expf(dt * a), h, dt * xt * Bv);
            sdt += dt;
        }
    }
    const int i = blk * 128 + tid;
    g_hp[c * 16384 + i] = h;
    g_ap[c * 16384 + i] = __expf(a * sdt);
}

__global__ __launch_bounds__(128) void scan_combine_kernel()
{
    const int i = blockIdx.x * 128 + threadIdx.x;
    float hp[NCHK], ap[NCHK];
    #pragma unroll
    for (int cc = 0; cc < NCHK; cc++) {
        hp[cc] = g_hp[cc * 16384 + i];
        ap[cc] = g_ap[cc * 16384 + i];
    }
    float hin = 0.f;
    #pragma unroll
    for (int cc = 0; cc < NCHK; cc++) {
        g_hin[cc * 16384 + i] = hin;
        hin = fmaf(ap[cc], hin, hp[cc]);
    }
}

__global__ __launch_bounds__(128) void scan_b_kernel(
    const float* __restrict__ x, const float* __restrict__ A_log,
    const float* __restrict__ Dv)
{
    extern __shared__ char smem[];
    const uint32_t sbase = smem_u32(smem);
    const int tid = threadIdx.x;
    const int blk = blockIdx.x;
    const int c   = blockIdx.y;
    const int lc = tid >> 4, s = tid & 15;
    const int d = blk * 8 + lc;
    const float a = -expf(A_log[d * DS + s]);
    const float Dd = Dv[d];
    const size_t tb = (size_t)c * CHK;

    const char* gB = (const char*)(g_bch + (size_t)blk * 128);
    const char* gC = (const char*)(g_bch + (size_t)DI * DS + (size_t)blk * 128);
    const char* gD = (const char*)(g_delta + (size_t)blk * 8);
    const char* gX = (const char*)(x + (size_t)blk * 8);

    #pragma unroll
    for (int st = 0; st < 4; st++) {
        const uint32_t soff = sbase + st * B_STAGE;
        const size_t t0 = tb + (size_t)st * SC_T;
        #pragma unroll
        for (int j = 0; j < 4; j++) {
            const int q = tid * 4 + j;
            const int stp = q >> 4, off = (q & 15) * 16;
            cp_async16(soff + stp * 256 + off, gB + (t0 + stp) * (BCW * 2) + off);
            cp_async16(soff + B_C_OFF + stp * 256 + off, gC + (t0 + stp) * (BCW * 2) + off);
        }
        {
            const int q = tid & 63;
            const int stp = q >> 1, off = (q & 1) * 16;
            if (tid < 64)
                cp_async16(soff + B_D_OFF + stp * 32 + off, gD + (t0 + stp) * (DI * 4) + off);
            else
                cp_async16(soff + B_X_OFF + stp * 32 + off, gX + (t0 + stp) * (DI * 4) + off);
        }
        CP_COMMIT();
    }

    float h = g_hin[c * 16384 + blk * 128 + tid];
    #pragma unroll
    for (int st = 0; st < 4; st++) {
        switch (st) {
            case 0: CP_WAIT(3); break;
            case 1: CP_WAIT(2); break;
            case 2: CP_WAIT(1); break;
            default: CP_WAIT(0); break;
        }
        __syncthreads();
        const uint32_t so = st * B_STAGE;
        const __half* sB = (const __half*)(smem + so);
        const __half* sC = (const __half*)(smem + so + B_C_OFF);
        const float* sD  = (const float*)(smem + so + B_D_OFF);
        const float* sX  = (const float*)(smem + so + B_X_OFF);
        const int tbase = (int)tb + st * SC_T;
        #pragma unroll 8
        for (int stp = 0; stp < SC_T; stp++) {
            const float Bv = __half2float(sB[stp * 128 + tid]);
            const float Cv = __half2float(sC[stp * 128 + tid]);
            const float dt = sD[stp * 8 + lc];
            const float xt = sX[stp * 8 + lc];
            h = fmaf(__expf(dt * a), h, dt * xt * Bv);
            float yv = h * Cv;
            yv += __shfl_xor_sync(0xffffffffu, yv, 1);
            yv += __shfl_xor_sync(0xffffffffu, yv, 2);
            yv += __shfl_xor_sync(0xffffffffu, yv, 4);
            yv += __shfl_xor_sync(0xffffffffu, yv, 8);
            if (s == 0)
                g_yf[(size_t)(tbase + stp) * DI + d] =
                    __float2half_rn(fmaf(xt, Dd, yv));
        }
    }
}

// ============================================================================
// Launch
// ============================================================================
extern "C" void kernel_launch(void* const* d_in, const int* in_sizes, int n_in,
                              void* d_out, int out_size)
{
    const float* x       = (const float*)d_in[0];
    const float* W_in    = (const float*)d_in[1];
    const float* W_delta = (const float*)d_in[2];
    const float* A_log   = (const float*)d_in[3];
    const float* Dv      = (const float*)d_in[4];
    const float* W_out   = (const float*)d_in[5];
    float* out = (float*)d_out;

    __half *bch, *xf, *wf, *wof, *yf;
    cudaGetSymbolAddress((void**)&bch, g_bch);
    cudaGetSymbolAddress((void**)&xf, g_xf);
    cudaGetSymbolAddress((void**)&wf, g_wf);
    cudaGetSymbolAddress((void**)&wof, g_wof);
    cudaGetSymbolAddress((void**)&yf, g_yf);

    cudaFuncSetAttribute(gemm_f16<__half>, cudaFuncAttributeMaxDynamicSharedMemorySize,
                         SMEM_F16_TOTAL);
    cudaFuncSetAttribute(gemm_f16<float>, cudaFuncAttributeMaxDynamicSharedMemorySize,
                         SMEM_F16_TOTAL);
    cudaFuncSetAttribute(scan_a_kernel, cudaFuncAttributeMaxDynamicSharedMemorySize,
                         SMEM_SCANA_TOTAL);
    cudaFuncSetAttribute(scan_b_kernel, cudaFuncAttributeMaxDynamicSharedMemorySize,
                         SMEM_SCANB_TOTAL);

    // 1) fused conversions (x, W_in[64:], W_out)
    cvt_all_kernel<<<(unsigned)((NALL4 + 255) / 256), 256>>>(x, W_in, W_out);
    // 2) B/C = x @ W_in[64:]^T  -> compact fp16 buffer
    {
        dim3 grid(L_SEQ / 128, BCW / 128);    // 16 x 256
        gemm_f16<__half><<<grid, 512, SMEM_F16_TOTAL>>>(xf, wf, bch, BCW);
    }
    // 3) exact fp32 delta_lr (128 CTAs)
    dlr_kernel<<<L_SEQ / 16, 256>>>(x, W_in);
    // 4) delta v2 (t-tile 32, vectorized)
    {
        dim3 grid(L_SEQ / 32, DI / 128);      // 64 x 8
        delta_kernel<<<grid, 128>>>(W_delta);
    }
    // 5) two-pass chunked scan
    {
        dim3 ga(128, NCHK);
        scan_a_kernel<<<ga, 128, SMEM_SCANA_TOTAL>>>(x, A_log);
        scan_combine_kernel<<<128, 128>>>();
        scan_b_kernel<<<ga, 128, SMEM_SCANB_TOTAL>>>(x, A_log, Dv);
    }
    // 6) out = y @ W_out^T  -> f32 output
    {
        dim3 grid(L_SEQ / 128, DM / 128);
        gemm_f16<float><<<grid, 512, SMEM_F16_TOTAL>>>(yf, wof, out, DM);
    }
}

// round 16
// speedup vs baseline: 1.1628x; 1.0058x over previous
#include <cuda_runtime.h>
#include <cuda_fp16.h>
#include <math.h>
#include <stdint.h>

// Problem constants
#define L_SEQ   2048
#define DM      1024
#define DI      1024
#define DTR     64
#define DS      16
#define PROJ    (DTR + 2 * DI * DS)   // 32832
#define BCW     32768                 // compact B/C width = 256 * 128
#define KDIM    1024

// -------- scratch (static device globals; no allocation) --------
__device__ __half g_bch[(size_t)L_SEQ * BCW];       // [B | C] per row, fp16
__device__ float  g_dlr[(size_t)L_SEQ * DTR];       // exact fp32 delta_lr
__device__ float  g_delta[(size_t)L_SEQ * DI];
__device__ __half g_xf[(size_t)L_SEQ * DM];
__device__ __half g_wf[(size_t)BCW * DM];           // W_in rows 64..32831
__device__ __half g_wof[(size_t)DM * DI];
__device__ __half g_yf[(size_t)L_SEQ * DI];
// two-pass scan intermediates: 16 chunks x 16384 (d,s) lanes
#define NCHK 16
#define CHK  (L_SEQ / NCHK)          // 128
__device__ float g_hp[NCHK * 16384];
__device__ float g_ap[NCHK * 16384];
__device__ float g_hin[NCHK * 16384];

// ============================================================================
// helpers
// ============================================================================
__device__ __forceinline__ uint32_t smem_u32(const void* p) {
    uint32_t a;
    asm("{ .reg .u64 t; cvta.to.shared.u64 t, %1; cvt.u32.u64 %0, t; }" : "=r"(a) : "l"(p));
    return a;
}
__device__ __forceinline__ uint32_t swz128(uint32_t o) { return o ^ ((o >> 3) & 0x70); }

__device__ __forceinline__ void cp_async16(uint32_t dst, const void* src) {
    asm volatile("cp.async.cg.shared.global [%0], [%1], 16;" :: "r"(dst), "l"(src));
}
#define CP_COMMIT() asm volatile("cp.async.commit_group;" ::: "memory")
#define CP_WAIT(n)  asm volatile("cp.async.wait_group %0;" :: "n"(n) : "memory")

__device__ __forceinline__ void ldsm4(uint32_t* r, uint32_t addr) {
    asm volatile("ldmatrix.sync.aligned.m8n8.x4.shared.b16 {%0,%1,%2,%3}, [%4];"
        : "=r"(r[0]), "=r"(r[1]), "=r"(r[2]), "=r"(r[3]) : "r"(addr));
}
__device__ __forceinline__ void mma_f16(float* d, const uint32_t* a, const uint32_t* b) {
    asm volatile(
        "mma.sync.aligned.m16n8k16.row.col.f32.f16.f16.f32 "
        "{%0,%1,%2,%3}, {%4,%5,%6,%7}, {%8,%9}, {%0,%1,%2,%3};"
        : "+f"(d[0]), "+f"(d[1]), "+f"(d[2]), "+f"(d[3])
        : "r"(a[0]), "r"(a[1]), "r"(a[2]), "r"(a[3]), "r"(b[0]), "r"(b[1]));
}

// ============================================================================
// Fused fp32 -> fp16 conversion v2: 8 floats/thread, single STG.128.
// Issue count per 8 floats: 2 LDG.128 + 4 CVT + 1 STG.128 + index ~ 10.
// ============================================================================
#define NX8   ((size_t)L_SEQ * DM / 8)
#define NW8   ((size_t)BCW * DM / 8)
#define NWO8  ((size_t)DM * DI / 8)
#define NALL8 (NX8 + NW8 + NWO8)

__global__ __launch_bounds__(256) void cvt_all_kernel(
    const float* __restrict__ x, const float* __restrict__ W_in,
    const float* __restrict__ W_out)
{
    size_t q = (size_t)blockIdx.x * 256 + threadIdx.x;   // unit = 8 floats
    if (q >= NALL8) return;
    const float* src;
    __half* dst;
    size_t i;
    if (q < NX8) { i = q * 8; src = x; dst = g_xf; }
    else if (q < NX8 + NW8) { i = (q - NX8) * 8; src = W_in + (size_t)DTR * DM; dst = g_wf; }
    else { i = (q - NX8 - NW8) * 8; src = W_out; dst = g_wof; }
    float4 v0 = *(const float4*)(src + i);
    float4 v1 = *(const float4*)(src + i + 4);
    __half2 h0 = __floats2half2_rn(v0.x, v0.y);
    __half2 h1 = __floats2half2_rn(v0.z, v0.w);
    __half2 h2 = __floats2half2_rn(v1.x, v1.y);
    __half2 h3 = __floats2half2_rn(v1.z, v1.w);
    uint4 pk;
    pk.x = *(uint32_t*)&h0; pk.y = *(uint32_t*)&h1;
    pk.z = *(uint32_t*)&h2; pk.w = *(uint32_t*)&h3;
    *(uint4*)(dst + i) = pk;
}

// ============================================================================
// FP16 GEMM v4 (unchanged): CTA 128x128, BK=64, 512 thr, 2 CTAs/SM,
// per-warp ks rotation, 3-stage cp.async pipeline, guard-free epilogue.
// ============================================================================
#define F_ATILE  16384
#define F_STAGE  32768
#define F_NSTAGE 3
#define SMEM_F16_TOTAL (F_NSTAGE * F_STAGE)   // 96 KB
#define F_NKC    (KDIM / 64)        // 16

template<typename OT>
__global__ __launch_bounds__(512, 2) void gemm_f16(
    const __half* __restrict__ A, const __half* __restrict__ B,
    OT* __restrict__ C, int ldc)
{
    extern __shared__ char smem[];
    const uint32_t sbase = smem_u32(smem);
    const int tid = threadIdx.x;
    const int wid = tid >> 5, lane = tid & 31;
    const int wm = wid & 3, wn = wid >> 2;

    const int m0 = blockIdx.x * 128;
    const int n0 = blockIdx.y * 128;

    float acc[2][4][4];
    #pragma unroll
    for (int i = 0; i < 2; i++)
        #pragma unroll
        for (int j = 0; j < 4; j++)
            #pragma unroll
            for (int q = 0; q < 4; q++) acc[i][j][q] = 0.f;

    auto issue = [&](int kc) {
        if (kc < F_NKC) {
            const uint32_t soff = sbase + (kc % F_NSTAGE) * F_STAGE;
            #pragma unroll
            for (int j = 0; j < 2; j++) {
                const int q = tid * 2 + j;
                const int row = q >> 3, c = q & 7;
                const uint32_t so = swz128((uint32_t)(row * 128 + c * 16));
                const size_t ga = (size_t)(m0 + row) * KDIM + (size_t)kc * 64 + c * 8;
                const size_t gb = (size_t)(n0 + row) * KDIM + (size_t)kc * 64 + c * 8;
                cp_async16(soff + so, A + ga);
                cp_async16(soff + F_ATILE + so, B + gb);
            }
        }
        CP_COMMIT();
    };

    const int rb_base = wn * 32 + ((lane >> 4) << 3) + (lane & 7);
    const int cb_half = (lane >> 3) & 1;
    const int ra_base = wm * 32 + (lane & 15);
    const int ca_half = lane >> 4;
    const int ksr = wn;

    issue(0);
    issue(1);

    #pragma unroll 1
    for (int kc = 0; kc < F_NKC; kc++) {
        if (kc + 1 < F_NKC) CP_WAIT(1); else CP_WAIT(0);
        __syncthreads();
        issue(kc + 2);

        const uint32_t sA = sbase + (kc % F_NSTAGE) * F_STAGE;

        #pragma unroll
        for (int kss = 0; kss < 4; kss++) {
            const int ks = (kss + ksr) & 3;
            uint32_t bf[4][2];
            #pragma unroll
            for (int p = 0; p < 2; p++) {
                const int rowb = rb_base + p * 16;
                const int chb  = ks * 2 + cb_half;
                ldsm4(&bf[p * 2][0],
                      sA + F_ATILE + swz128((uint32_t)(rowb * 128 + chb * 16)));
            }
            #pragma unroll
            for (int mf = 0; mf < 2; mf++) {
                const int rowa = ra_base + mf * 16;
                const int cha  = ks * 2 + ca_half;
                uint32_t af[4];
                ldsm4(af, sA + swz128((uint32_t)(rowa * 128 + cha * 16)));
                #pragma unroll
                for (int nf = 0; nf < 4; nf++) mma_f16(acc[mf][nf], af, bf[nf]);
            }
        }
    }

    const int g = lane >> 2, t4 = lane & 3;
    #pragma unroll
    for (int mf = 0; mf < 2; mf++) {
        #pragma unroll
        for (int nf = 0; nf < 4; nf++) {
            const int m = m0 + wm * 32 + mf * 16 + g;
            const int n = n0 + wn * 32 + nf * 8 + t4 * 2;
            if constexpr (sizeof(OT) == 2) {
                *(__half2*)((__half*)C + (size_t)m * ldc + n) =
                    __floats2half2_rn(acc[mf][nf][0], acc[mf][nf][1]);
                *(__half2*)((__half*)C + (size_t)(m + 8) * ldc + n) =
                    __floats2half2_rn(acc[mf][nf][2], acc[mf][nf][3]);
            } else {
                *(float2*)((float*)C + (size_t)m * ldc + n) =
                    make_float2(acc[mf][nf][0], acc[mf][nf][1]);
                *(float2*)((float*)C + (size_t)(m + 8) * ldc + n) =
                    make_float2(acc[mf][nf][2], acc[mf][nf][3]);
            }
        }
    }
}

// ============================================================================
// Exact fp32 delta_lr: dlr[t,k] = x[t,:]·W_in[k,:]  — 128 CTAs (16 t-rows each)
// ============================================================================
__global__ __launch_bounds__(256) void dlr_kernel(
    const float* __restrict__ x, const float* __restrict__ W_in)
{
    __shared__ float sx[64][17];
    __shared__ float sw[64][65];
    const int tid = threadIdx.x;
    const int k = tid & 63;
    const int tg = tid >> 6;
    const int t0 = blockIdx.x * 16;

    float acc[4];
    #pragma unroll
    for (int i = 0; i < 4; i++) acc[i] = 0.f;

    for (int kc = 0; kc < 16; kc++) {
        {
            const int t = tid >> 4, c = tid & 15;
            float4 v = *(const float4*)(x + (size_t)(t0 + t) * KDIM + kc * 64 + c * 4);
            sx[c * 4 + 0][t] = v.x; sx[c * 4 + 1][t] = v.y;
            sx[c * 4 + 2][t] = v.z; sx[c * 4 + 3][t] = v.w;
        }
        #pragma unroll
        for (int j = 0; j < 4; j++) {
            const int q = tid * 4 + j;
            const int k2 = q >> 4, c = q & 15;
            float4 v = *(const float4*)(W_in + (size_t)k2 * KDIM + kc * 64 + c * 4);
            sw[c * 4 + 0][k2] = v.x; sw[c * 4 + 1][k2] = v.y;
            sw[c * 4 + 2][k2] = v.z; sw[c * 4 + 3][k2] = v.w;
        }
        __syncthreads();
        #pragma unroll 16
        for (int kk = 0; kk < 64; kk++) {
            const float w = sw[kk][k];
            #pragma unroll
            for (int i = 0; i < 4; i++)
                acc[i] = fmaf(sx[kk][tg * 4 + i], w, acc[i]);
        }
        __syncthreads();
    }
    #pragma unroll
    for (int i = 0; i < 4; i++)
        g_dlr[(size_t)(t0 + tg * 4 + i) * DTR + k] = acc[i];
}

// ============================================================================
// delta v3: t-tile 16, grid (128, 8) = 1024 CTAs for latency hiding.
// float4 dl loads (LDS.128 broadcast) + 4 scalar w per 4-kk step.
// ============================================================================
__global__ __launch_bounds__(128) void delta_kernel(const float* __restrict__ W_delta)
{
    __shared__ float s_dl[16][64];       // [t][kk]
    __shared__ float s_wT[64][129];      // [kk][d], padded
    const int tid = threadIdx.x;
    const int t0 = blockIdx.x * 16;
    const int d0 = blockIdx.y * 128;

    // load dlr tile: 16 t x 64 kk = 256 float4, 2 per thread
    #pragma unroll
    for (int j = 0; j < 2; j++) {
        const int q = tid * 2 + j;           // 0..255
        const int t = q >> 4, c = q & 15;
        float4 v = *(const float4*)(g_dlr + (size_t)(t0 + t) * DTR + c * 4);
        *(float4*)&s_dl[t][c * 4] = v;
    }
    // load W tile: 128 d x 64 kk = 2048 float4, 16 per thread (transpose)
    #pragma unroll
    for (int j = 0; j < 16; j++) {
        const int q = tid * 16 + j;          // 0..2047
        const int d = q >> 4, c = q & 15;
        float4 v = *(const float4*)(W_delta + (size_t)(d0 + d) * DTR + c * 4);
        s_wT[c * 4 + 0][d] = v.x; s_wT[c * 4 + 1][d] = v.y;
        s_wT[c * 4 + 2][d] = v.z; s_wT[c * 4 + 3][d] = v.w;
    }
    __syncthreads();

    float accv[16];
    #pragma unroll
    for (int t = 0; t < 16; t++) accv[t] = 0.f;

    #pragma unroll 4
    for (int k4 = 0; k4 < 16; k4++) {
        const float w0 = s_wT[k4 * 4 + 0][tid];
        const float w1 = s_wT[k4 * 4 + 1][tid];
        const float w2 = s_wT[k4 * 4 + 2][tid];
        const float w3 = s_wT[k4 * 4 + 3][tid];
        #pragma unroll
        for (int t = 0; t < 16; t++) {
            const float4 dl = *(const float4*)&s_dl[t][k4 * 4];
            float a = fmaf(dl.x, w0, accv[t]);
            a = fmaf(dl.y, w1, a);
            a = fmaf(dl.z, w2, a);
            accv[t] = fmaf(dl.w, w3, a);
        }
    }
    #pragma unroll
    for (int t = 0; t < 16; t++) {
        const float z = accv[t];
        const float sp = fmaxf(z, 0.f) + log1pf(__expf(-fabsf(z)));
        g_delta[(size_t)(t0 + t) * DI + d0 + tid] = sp;
    }
}

// ============================================================================
// Two-pass chunked scan (unchanged).
// ============================================================================
#define SC_T      32
#define SC_BBYTES (SC_T * 256)
#define SC_DBYTES (SC_T * 32)
#define A_D_OFF   SC_BBYTES
#define A_X_OFF   (SC_BBYTES + SC_DBYTES)
#define A_STAGE   (SC_BBYTES + 2 * SC_DBYTES)
#define SMEM_SCANA_TOTAL (4 * A_STAGE)
#define B_C_OFF   SC_BBYTES
#define B_D_OFF   (2 * SC_BBYTES)
#define B_X_OFF   (2 * SC_BBYTES + SC_DBYTES)
#define B_STAGE   (2 * SC_BBYTES + 2 * SC_DBYTES)
#define SMEM_SCANB_TOTAL (4 * B_STAGE)

__global__ __launch_bounds__(128) void scan_a_kernel(
    const float* __restrict__ x, const float* __restrict__ A_log)
{
    extern __shared__ char smem[];
    const uint32_t sbase = smem_u32(smem);
    const int tid = threadIdx.x;
    const int blk = blockIdx.x;
    const int c   = blockIdx.y;
    const int lc = tid >> 4, s = tid & 15;
    const int d = blk * 8 + lc;
    const float a = -expf(A_log[d * DS + s]);
    const size_t tb = (size_t)c * CHK;

    const char* gB = (const char*)(g_bch + (size_t)blk * 128);
    const char* gD = (const char*)(g_delta + (size_t)blk * 8);
    const char* gX = (const char*)(x + (size_t)blk * 8);

    #pragma unroll
    for (int st = 0; st < 4; st++) {
        const uint32_t soff = sbase + st * A_STAGE;
        const size_t t0 = tb + (size_t)st * SC_T;
        #pragma unroll
        for (int j = 0; j < 4; j++) {
            const int q = tid * 4 + j;
            const int stp = q >> 4, off = (q & 15) * 16;
            cp_async16(soff + stp * 256 + off, gB + (t0 + stp) * (BCW * 2) + off);
        }
        {
            const int q = tid & 63;
            const int stp = q >> 1, off = (q & 1) * 16;
            if (tid < 64)
                cp_async16(soff + A_D_OFF + stp * 32 + off, gD + (t0 + stp) * (DI * 4) + off);
            else
                cp_async16(soff + A_X_OFF + stp * 32 + off, gX + (t0 + stp) * (DI * 4) + off);
        }
        CP_COMMIT();
    }

    float h = 0.f, sdt = 0.f;
    #pragma unroll
    for (int st = 0; st < 4; st++) {
        switch (st) {
            case 0: CP_WAIT(3); break;
            case 1: CP_WAIT(2); break;
            case 2: CP_WAIT(1); break;
            default: CP_WAIT(0); break;
        }
        __syncthreads();
        const uint32_t so = st * A_STAGE;
        const __half* sB = (const __half*)(smem + so);
        const float* sD  = (const float*)(smem + so + A_D_OFF);
        const float* sX  = (const float*)(smem + so + A_X_OFF);
        #pragma unroll 8
        for (int stp = 0; stp < SC_T; stp++) {
            const float Bv = __half2float(sB[stp * 128 + tid]);
            const float dt = sD[stp * 8 + lc];
            const float xt = sX[stp * 8 + lc];
            h = fmaf(__expf(dt * a), h, dt * xt * Bv);
            sdt += dt;
        }
    }
    const int i = blk * 128 + tid;
    g_hp[c * 16384 + i] = h;
    g_ap[c * 16384 + i] = __expf(a * sdt);
}

__global__ __launch_bounds__(128) void scan_combine_kernel()
{
    const int i = blockIdx.x * 128 + threadIdx.x;
    float hp[NCHK], ap[NCHK];
    #pragma unroll
    for (int cc = 0; cc < NCHK; cc++) {
        hp[cc] = g_hp[cc * 16384 + i];
        ap[cc] = g_ap[cc * 16384 + i];
    }
    float hin = 0.f;
    #pragma unroll
    for (int cc = 0; cc < NCHK; cc++) {
        g_hin[cc * 16384 + i] = hin;
        hin = fmaf(ap[cc], hin, hp[cc]);
    }
}

__global__ __launch_bounds__(128) void scan_b_kernel(
    const float* __restrict__ x, const float* __restrict__ A_log,
    const float* __restrict__ Dv)
{
    extern __shared__ char smem[];
    const uint32_t sbase = smem_u32(smem);
    const int tid = threadIdx.x;
    const int blk = blockIdx.x;
    const int c   = blockIdx.y;
    const int lc = tid >> 4, s = tid & 15;
    const int d = blk * 8 + lc;
    const float a = -expf(A_log[d * DS + s]);
    const float Dd = Dv[d];
    const size_t tb = (size_t)c * CHK;

    const char* gB = (const char*)(g_bch + (size_t)blk * 128);
    const char* gC = (const char*)(g_bch + (size_t)DI * DS + (size_t)blk * 128);
    const char* gD = (const char*)(g_delta + (size_t)blk * 8);
    const char* gX = (const char*)(x + (size_t)blk * 8);

    #pragma unroll
    for (int st = 0; st < 4; st++) {
        const uint32_t soff = sbase + st * B_STAGE;
        const size_t t0 = tb + (size_t)st * SC_T;
        #pragma unroll
        for (int j = 0; j < 4; j++) {
            const int q = tid * 4 + j;
            const int stp = q >> 4, off = (q & 15) * 16;
            cp_async16(soff + stp * 256 + off, gB + (t0 + stp) * (BCW * 2) + off);
            cp_async16(soff + B_C_OFF + stp * 256 + off, gC + (t0 + stp) * (BCW * 2) + off);
        }
        {
            const int q = tid & 63;
            const int stp = q >> 1, off = (q & 1) * 16;
            if (tid < 64)
                cp_async16(soff + B_D_OFF + stp * 32 + off, gD + (t0 + stp) * (DI * 4) + off);
            else
                cp_async16(soff + B_X_OFF + stp * 32 + off, gX + (t0 + stp) * (DI * 4) + off);
        }
        CP_COMMIT();
    }

    float h = g_hin[c * 16384 + blk * 128 + tid];
    #pragma unroll
    for (int st = 0; st < 4; st++) {
        switch (st) {
            case 0: CP_WAIT(3); break;
            case 1: CP_WAIT(2); break;
            case 2: CP_WAIT(1); break;
            default: CP_WAIT(0); break;
        }
        __syncthreads();
        const uint32_t so = st * B_STAGE;
        const __half* sB = (const __half*)(smem + so);
        const __half* sC = (const __half*)(smem + so + B_C_OFF);
        const float* sD  = (const float*)(smem + so + B_D_OFF);
        const float* sX  = (const float*)(smem + so + B_X_OFF);
        const int tbase = (int)tb + st * SC_T;
        #pragma unroll 8
        for (int stp = 0; stp < SC_T; stp++) {
            const float Bv = __half2float(sB[stp * 128 + tid]);
            const float Cv = __half2float(sC[stp * 128 + tid]);
            const float dt = sD[stp * 8 + lc];
            const float xt = sX[stp * 8 + lc];
            h = fmaf(__expf(dt * a), h, dt * xt * Bv);
            float yv = h * Cv;
            yv += __shfl_xor_sync(0xffffffffu, yv, 1);
            yv += __shfl_xor_sync(0xffffffffu, yv, 2);
            yv += __shfl_xor_sync(0xffffffffu, yv, 4);
            yv += __shfl_xor_sync(0xffffffffu, yv, 8);
            if (s == 0)
                g_yf[(size_t)(tbase + stp) * DI + d] =
                    __float2half_rn(fmaf(xt, Dd, yv));
        }
    }
}

// ============================================================================
// Launch
// ============================================================================
extern "C" void kernel_launch(void* const* d_in, const int* in_sizes, int n_in,
                              void* d_out, int out_size)
{
    const float* x       = (const float*)d_in[0];
    const float* W_in    = (const float*)d_in[1];
    const float* W_delta = (const float*)d_in[2];
    const float* A_log   = (const float*)d_in[3];
    const float* Dv      = (const float*)d_in[4];
    const float* W_out   = (const float*)d_in[5];
    float* out = (float*)d_out;

    __half *bch, *xf, *wf, *wof, *yf;
    cudaGetSymbolAddress((void**)&bch, g_bch);
    cudaGetSymbolAddress((void**)&xf, g_xf);
    cudaGetSymbolAddress((void**)&wf, g_wf);
    cudaGetSymbolAddress((void**)&wof, g_wof);
    cudaGetSymbolAddress((void**)&yf, g_yf);

    cudaFuncSetAttribute(gemm_f16<__half>, cudaFuncAttributeMaxDynamicSharedMemorySize,
                         SMEM_F16_TOTAL);
    cudaFuncSetAttribute(gemm_f16<float>, cudaFuncAttributeMaxDynamicSharedMemorySize,
                         SMEM_F16_TOTAL);
    cudaFuncSetAttribute(scan_a_kernel, cudaFuncAttributeMaxDynamicSharedMemorySize,
                         SMEM_SCANA_TOTAL);
    cudaFuncSetAttribute(scan_b_kernel, cudaFuncAttributeMaxDynamicSharedMemorySize,
                         SMEM_SCANB_TOTAL);

    // 1) fused conversions v2 (x, W_in[64:], W_out) — 8 floats/thread
    cvt_all_kernel<<<(unsigned)((NALL8 + 255) / 256), 256>>>(x, W_in, W_out);
    // 2) B/C = x @ W_in[64:]^T  -> compact fp16 buffer
    {
        dim3 grid(L_SEQ / 128, BCW / 128);    // 16 x 256
        gemm_f16<__half><<<grid, 512, SMEM_F16_TOTAL>>>(xf, wf, bch, BCW);
    }
    // 3) exact fp32 delta_lr (128 CTAs)
    dlr_kernel<<<L_SEQ / 16, 256>>>(x, W_in);
    // 4) delta v3 (t-tile 16, 1024 CTAs)
    {
        dim3 grid(L_SEQ / 16, DI / 128);      // 128 x 8
        delta_kernel<<<grid, 128>>>(W_delta);
    }
    // 5) two-pass chunked scan
    {
        dim3 ga(128, NCHK);
        scan_a_kernel<<<ga, 128, SMEM_SCANA_TOTAL>>>(x, A_log);
        scan_combine_kernel<<<128, 128>>>();
        scan_b_kernel<<<ga, 128, SMEM_SCANB_TOTAL>>>(x, A_log, Dv);
    }
    // 6) out = y @ W_out^T  -> f32 output
    {
        dim3 grid(L_SEQ / 128, DM / 128);
        gemm_f16<float><<<grid, 512, SMEM_F16_TOTAL>>>(yf, wof, out, DM);
    }
}